// round 7
// baseline (speedup 1.0000x reference)
#include <cuda_runtime.h>
#include <math.h>
#include <stdint.h>

#define SEQ     2048
#define DMODEL  2048
#define NHEAD   16
#define FFDIM   8192
#define NTOK    4096
#define LN_EPS  1e-5f

__device__ float g_h  [(size_t)NTOK * DMODEL];
__device__ float g_qkv[(size_t)NTOK * 3 * DMODEL];
__device__ float g_av [(size_t)NTOK * DMODEL];
__device__ float g_x1 [(size_t)NTOK * DMODEL];
__device__ float g_ffn[(size_t)NTOK * FFDIM];
__device__ float g_wqkv_r[(size_t)3 * DMODEL * DMODEL];
__device__ float g_wout_r[(size_t)DMODEL * DMODEL];
__device__ float g_w1_r  [(size_t)DMODEL * FFDIM];
__device__ float g_w2_r  [(size_t)FFDIM * DMODEL];

// ---------------- helpers ----------------
__device__ __forceinline__ float tf32r(float x){
  uint32_t u; asm("cvt.rna.tf32.f32 %0, %1;" : "=r"(u) : "f"(x));
  return __uint_as_float(u);
}
__device__ __forceinline__ uint32_t s2u(const void* p){
  uint32_t a;
  asm("{ .reg .u64 t; cvta.to.shared.u64 t, %1; cvt.u32.u64 %0, t; }" : "=r"(a) : "l"(p));
  return a;
}
__device__ __forceinline__ void cpa16(uint32_t dst, const void* src){
  asm volatile("cp.async.cg.shared.global [%0], [%1], 16;" :: "r"(dst), "l"(src));
}
__device__ __forceinline__ void cp_commit(){ asm volatile("cp.async.commit_group;"); }
__device__ __forceinline__ void cp_wait0(){ asm volatile("cp.async.wait_group 0;" ::: "memory"); }
__device__ __forceinline__ void cp_wait1(){ asm volatile("cp.async.wait_group 1;" ::: "memory"); }
__device__ __forceinline__ void mma8(float* c, const uint32_t* a, const uint32_t* b){
  asm volatile("mma.sync.aligned.m16n8k8.row.col.f32.tf32.tf32.f32 "
    "{%0,%1,%2,%3}, {%4,%5,%6,%7}, {%8,%9}, {%0,%1,%2,%3};"
    : "+f"(c[0]), "+f"(c[1]), "+f"(c[2]), "+f"(c[3])
    : "r"(a[0]), "r"(a[1]), "r"(a[2]), "r"(a[3]), "r"(b[0]), "r"(b[1]));
}
__device__ __forceinline__ float gelu_exact(float t){
  return 0.5f * t * (1.0f + erff(t * 0.70710678118654752f));
}

// ---- single fused tf32 round pass over all 4 weight matrices ----
#define RW_QKV_F4 (3 * DMODEL * DMODEL / 4)
#define RW_OUT_F4 (DMODEL * DMODEL / 4)
#define RW_W1_F4  (DMODEL * FFDIM / 4)
#define RW_W2_F4  (FFDIM * DMODEL / 4)
#define RW_TOTAL_F4 (RW_QKV_F4 + RW_OUT_F4 + RW_W1_F4 + RW_W2_F4)

__global__ __launch_bounds__(256) void round_all_kernel(
    const float4* __restrict__ qkv_w, float4* __restrict__ qkv_o,
    const float4* __restrict__ out_w, float4* __restrict__ out_o,
    const float4* __restrict__ w1,    float4* __restrict__ w1_o,
    const float4* __restrict__ w2,    float4* __restrict__ w2_o)
{
  size_t i = (size_t)blockIdx.x * 256 + threadIdx.x;
  const float4* src; float4* dst; size_t off;
  if (i < RW_QKV_F4){ src = qkv_w; dst = qkv_o; off = i; }
  else if (i < RW_QKV_F4 + RW_OUT_F4){ src = out_w; dst = out_o; off = i - RW_QKV_F4; }
  else if (i < RW_QKV_F4 + RW_OUT_F4 + RW_W1_F4){ src = w1; dst = w1_o; off = i - RW_QKV_F4 - RW_OUT_F4; }
  else { src = w2; dst = w2_o; off = i - RW_QKV_F4 - RW_OUT_F4 - RW_W1_F4; }
  float4 v = src[off];
  v.x = tf32r(v.x); v.y = tf32r(v.y); v.z = tf32r(v.z); v.w = tf32r(v.w);
  dst[off] = v;
}

// ---- LayerNorm -> row-major tf32-rounded ----
__global__ __launch_bounds__(256) void ln_kernel(
    const float* __restrict__ x, const float* __restrict__ gamma,
    const float* __restrict__ beta, float* __restrict__ out)
{
  int row = blockIdx.x;
  int tid = threadIdx.x;
  const float4* xr = (const float4*)(x + (size_t)row * DMODEL);
  float4 v0 = xr[tid];
  float4 v1 = xr[tid + 256];
  float s  = v0.x + v0.y + v0.z + v0.w + v1.x + v1.y + v1.z + v1.w;
  float sq = v0.x*v0.x + v0.y*v0.y + v0.z*v0.z + v0.w*v0.w
           + v1.x*v1.x + v1.y*v1.y + v1.z*v1.z + v1.w*v1.w;
  #pragma unroll
  for (int m = 16; m > 0; m >>= 1){
    s  += __shfl_xor_sync(0xffffffffu, s,  m);
    sq += __shfl_xor_sync(0xffffffffu, sq, m);
  }
  __shared__ float red_s[8], red_q[8], bc[2];
  int warp = tid >> 5, lane = tid & 31;
  if (lane == 0){ red_s[warp] = s; red_q[warp] = sq; }
  __syncthreads();
  if (tid == 0){
    float ts = 0.f, tq = 0.f;
    #pragma unroll
    for (int i = 0; i < 8; i++){ ts += red_s[i]; tq += red_q[i]; }
    float mu  = ts * (1.0f / DMODEL);
    float var = tq * (1.0f / DMODEL) - mu * mu;
    bc[0] = mu; bc[1] = rsqrtf(var + LN_EPS);
  }
  __syncthreads();
  float mu = bc[0], rinv = bc[1];
  const float4* gv = (const float4*)gamma;
  const float4* bv = (const float4*)beta;
  float4 g0 = gv[tid], b0 = bv[tid];
  float4 g1 = gv[tid + 256], b1 = bv[tid + 256];
  float4 o0, o1;
  o0.x = tf32r((v0.x - mu) * rinv * g0.x + b0.x);
  o0.y = tf32r((v0.y - mu) * rinv * g0.y + b0.y);
  o0.z = tf32r((v0.z - mu) * rinv * g0.z + b0.z);
  o0.w = tf32r((v0.w - mu) * rinv * g0.w + b0.w);
  o1.x = tf32r((v1.x - mu) * rinv * g1.x + b1.x);
  o1.y = tf32r((v1.y - mu) * rinv * g1.y + b1.y);
  o1.z = tf32r((v1.z - mu) * rinv * g1.z + b1.z);
  o1.w = tf32r((v1.w - mu) * rinv * g1.w + b1.w);
  float4* ov = (float4*)(out + (size_t)row * DMODEL);
  ov[tid]       = o0;
  ov[tid + 256] = o1;
}

// ---------------------------------------------------------------------------
// tf32 mma.sync GEMM v1: 128x128 tile, occ 2 (for narrow-N GEMMs; better wave
// quantization). 8 warps 2x4, warp tile 64x32. 2-stage cp.async.
// ---------------------------------------------------------------------------
template<int EPI, int ROUT>
__global__ __launch_bounds__(256, 2) void tfgemm(
    const float* __restrict__ A, const float* __restrict__ B,
    const float* __restrict__ bias, const float* __restrict__ res,
    float* __restrict__ C, int M, int N, int K)
{
  __shared__ float As[2][128][20];
  __shared__ float Bs[2][16][136];

  int tid = threadIdx.x, lane = tid & 31, warp = tid >> 5;
  int bx = blockIdx.x, by = blockIdx.y;
  int wm = (warp >> 2) * 64, wn = (warp & 3) * 32;
  int gid = lane >> 2, tig = lane & 3;

  int a_r0 = tid >> 2;
  int a_k4 = (tid & 3) * 4;
  int b_k0 = tid >> 5;
  int b_n4 = (tid & 31) * 4;

  const float* Ag = A + (size_t)(by * 128 + a_r0) * K + a_k4;
  const float* Bg = B + (size_t)b_k0 * N + bx * 128 + b_n4;

  uint32_t as_d0 = s2u(&As[0][a_r0][a_k4]);
  uint32_t as_d1 = s2u(&As[0][a_r0 + 64][a_k4]);
  uint32_t bs_d0 = s2u(&Bs[0][b_k0][b_n4]);
  uint32_t bs_d1 = s2u(&Bs[0][b_k0 + 8][b_n4]);
  const uint32_t aSt = sizeof(float) * 128 * 20;
  const uint32_t bSt = sizeof(float) * 16 * 136;

  float c[4][4][4];
  #pragma unroll
  for (int mi = 0; mi < 4; mi++)
    #pragma unroll
    for (int ni = 0; ni < 4; ni++)
      #pragma unroll
      for (int q = 0; q < 4; q++) c[mi][ni][q] = 0.f;

  int nk = K >> 4;
  cpa16(as_d0, Ag);
  cpa16(as_d1, Ag + (size_t)64 * K);
  cpa16(bs_d0, Bg);
  cpa16(bs_d1, Bg + (size_t)8 * N);
  cp_commit();

  int st = 0;
  for (int kb = 0; kb < nk; kb++){
    cp_wait0();
    __syncthreads();
    if (kb + 1 < nk){
      const float* Agn = Ag + (kb + 1) * 16;
      const float* Bgn = Bg + (size_t)(kb + 1) * 16 * N;
      uint32_t so = (st ^ 1) ? aSt : 0;
      uint32_t sb = (st ^ 1) ? bSt : 0;
      cpa16(as_d0 + so, Agn);
      cpa16(as_d1 + so, Agn + (size_t)64 * K);
      cpa16(bs_d0 + sb, Bgn);
      cpa16(bs_d1 + sb, Bgn + (size_t)8 * N);
      cp_commit();
    }
    #pragma unroll
    for (int ks = 0; ks < 2; ks++){
      int k0 = ks * 8;
      uint32_t a[4][4], b[4][2];
      #pragma unroll
      for (int mi = 0; mi < 4; mi++){
        int r0 = wm + mi * 16 + gid;
        a[mi][0] = __float_as_uint(As[st][r0][k0 + tig]);
        a[mi][1] = __float_as_uint(As[st][r0 + 8][k0 + tig]);
        a[mi][2] = __float_as_uint(As[st][r0][k0 + tig + 4]);
        a[mi][3] = __float_as_uint(As[st][r0 + 8][k0 + tig + 4]);
      }
      #pragma unroll
      for (int ni = 0; ni < 4; ni++){
        int n0 = wn + ni * 8 + gid;
        b[ni][0] = __float_as_uint(Bs[st][k0 + tig][n0]);
        b[ni][1] = __float_as_uint(Bs[st][k0 + tig + 4][n0]);
      }
      #pragma unroll
      for (int mi = 0; mi < 4; mi++)
        #pragma unroll
        for (int ni = 0; ni < 4; ni++)
          mma8(c[mi][ni], a[mi], b[ni]);
    }
    st ^= 1;
    __syncthreads();
  }

  #pragma unroll
  for (int ni = 0; ni < 4; ni++){
    int col = bx * 128 + wn + ni * 8 + 2 * tig;
    float bb0 = bias[col], bb1 = bias[col + 1];
    #pragma unroll
    for (int mi = 0; mi < 4; mi++){
      int row0 = by * 128 + wm + mi * 16 + gid;
      float2 v0, v1;
      v0.x = c[mi][ni][0] + bb0; v0.y = c[mi][ni][1] + bb1;
      v1.x = c[mi][ni][2] + bb0; v1.y = c[mi][ni][3] + bb1;
      if (EPI == 1){
        v0.x = gelu_exact(v0.x); v0.y = gelu_exact(v0.y);
        v1.x = gelu_exact(v1.x); v1.y = gelu_exact(v1.y);
      }
      if (EPI == 2){
        float2 r0 = *(const float2*)&res[(size_t)row0 * N + col];
        float2 r1 = *(const float2*)&res[(size_t)(row0 + 8) * N + col];
        v0.x += r0.x; v0.y += r0.y;
        v1.x += r1.x; v1.y += r1.y;
      }
      if (ROUT){
        v0.x = tf32r(v0.x); v0.y = tf32r(v0.y);
        v1.x = tf32r(v1.x); v1.y = tf32r(v1.y);
      }
      *(float2*)&C[(size_t)row0 * N + col]       = v0;
      *(float2*)&C[(size_t)(row0 + 8) * N + col] = v1;
    }
  }
}

// ---------------------------------------------------------------------------
// tf32 mma.sync GEMM v2: 128x256 tile, occ 1, 3-stage (for wide-N GEMMs).
// ---------------------------------------------------------------------------
#define G2_AF    (128 * 20)
#define G2_BF    (16 * 264)
#define G2_STF   (G2_AF + G2_BF)
#define G2_SMEM  (3 * G2_STF * 4)

template<int EPI, int ROUT>
__global__ __launch_bounds__(256, 1) void tfgemm2(
    const float* __restrict__ A, const float* __restrict__ B,
    const float* __restrict__ bias, const float* __restrict__ res,
    float* __restrict__ C, int M, int N, int K)
{
  extern __shared__ float sm[];
  int tid = threadIdx.x, lane = tid & 31, warp = tid >> 5;
  int bx = blockIdx.x, by = blockIdx.y;
  int wm = (warp >> 2) * 64, wn = (warp & 3) * 64;
  int gid = lane >> 2, tig = lane & 3;

  int a_r0 = tid >> 2;
  int a_k4 = (tid & 3) * 4;
  int b_k0 = tid >> 6;
  int b_n4 = (tid & 63) * 4;

  const float* Ag = A + (size_t)(by * 128 + a_r0) * K + a_k4;
  const float* Bg = B + (size_t)b_k0 * N + bx * 256 + b_n4;

  uint32_t smb = s2u(sm);
  uint32_t asd0 = smb + (a_r0 * 20 + a_k4) * 4;
  uint32_t asd1 = smb + ((a_r0 + 64) * 20 + a_k4) * 4;
  uint32_t bsd  = smb + (G2_AF + b_k0 * 264 + b_n4) * 4;

  float c[4][8][4];
  #pragma unroll
  for (int mi = 0; mi < 4; mi++)
    #pragma unroll
    for (int ni = 0; ni < 8; ni++)
      #pragma unroll
      for (int q = 0; q < 4; q++) c[mi][ni][q] = 0.f;

  int nk = K >> 4;

  auto issue = [&](int kb, int st){
    uint32_t off = (uint32_t)st * G2_STF * 4;
    const float* Agn = Ag + kb * 16;
    const float* Bgn = Bg + (size_t)kb * 16 * N;
    cpa16(asd0 + off, Agn);
    cpa16(asd1 + off, Agn + (size_t)64 * K);
    #pragma unroll
    for (int i = 0; i < 4; i++)
      cpa16(bsd + off + i * 4 * 264 * 4, Bgn + (size_t)(4 * i) * N);
    cp_commit();
  };

  issue(0, 0);
  if (nk > 1) issue(1, 1);

  for (int kb = 0; kb < nk; kb++){
    int st = kb % 3;
    if (kb + 1 < nk) cp_wait1(); else cp_wait0();
    __syncthreads();

    const float* As = sm + st * G2_STF;
    const float* Bs = As + G2_AF;
    #pragma unroll
    for (int ks = 0; ks < 2; ks++){
      int k0 = ks * 8;
      uint32_t a[4][4], b[8][2];
      #pragma unroll
      for (int mi = 0; mi < 4; mi++){
        int r0 = wm + mi * 16 + gid;
        a[mi][0] = __float_as_uint(As[r0 * 20 + k0 + tig]);
        a[mi][1] = __float_as_uint(As[(r0 + 8) * 20 + k0 + tig]);
        a[mi][2] = __float_as_uint(As[r0 * 20 + k0 + tig + 4]);
        a[mi][3] = __float_as_uint(As[(r0 + 8) * 20 + k0 + tig + 4]);
      }
      #pragma unroll
      for (int t = 0; t < 8; t++){
        int n0 = wn + 8 * t + gid;
        b[t][0] = __float_as_uint(Bs[(k0 + tig) * 264 + n0]);
        b[t][1] = __float_as_uint(Bs[(k0 + tig + 4) * 264 + n0]);
      }
      #pragma unroll
      for (int mi = 0; mi < 4; mi++)
        #pragma unroll
        for (int t = 0; t < 8; t++)
          mma8(c[mi][t], a[mi], b[t]);
    }
    __syncthreads();
    if (kb + 2 < nk) issue(kb + 2, (kb + 2) % 3);
  }

  #pragma unroll
  for (int ni = 0; ni < 8; ni++){
    int col = bx * 256 + wn + ni * 8 + 2 * tig;
    float bb0 = bias[col], bb1 = bias[col + 1];
    #pragma unroll
    for (int mi = 0; mi < 4; mi++){
      int row0 = by * 128 + wm + mi * 16 + gid;
      float2 v0, v1;
      v0.x = c[mi][ni][0] + bb0; v0.y = c[mi][ni][1] + bb1;
      v1.x = c[mi][ni][2] + bb0; v1.y = c[mi][ni][3] + bb1;
      if (EPI == 1){
        v0.x = gelu_exact(v0.x); v0.y = gelu_exact(v0.y);
        v1.x = gelu_exact(v1.x); v1.y = gelu_exact(v1.y);
      }
      if (EPI == 2){
        float2 r0 = *(const float2*)&res[(size_t)row0 * N + col];
        float2 r1 = *(const float2*)&res[(size_t)(row0 + 8) * N + col];
        v0.x += r0.x; v0.y += r0.y;
        v1.x += r1.x; v1.y += r1.y;
      }
      if (ROUT){
        v0.x = tf32r(v0.x); v0.y = tf32r(v0.y);
        v1.x = tf32r(v1.x); v1.y = tf32r(v1.y);
      }
      *(float2*)&C[(size_t)row0 * N + col]       = v0;
      *(float2*)&C[(size_t)(row0 + 8) * N + col] = v1;
    }
  }
}

// ---------------------------------------------------------------------------
// tf32 mma.sync flash attention (R5 design) + heavy-first qt remap.
// ---------------------------------------------------------------------------
#define AT_TILE_F  8448
#define AT_BUF_F   16896
#define AT_PS_F    33792
#define AT_SMEM    ((AT_PS_F + 128 * 68) * 4)

__global__ __launch_bounds__(256, 1) void attn_mma_kernel(
    const float* __restrict__ qkv, float* __restrict__ av)
{
  extern __shared__ float sm[];
  float* Ps = sm + AT_PS_F;
  uint32_t sbase = s2u(sm);

  // heavy-first: largest qt launches first for tail packing
  int qt = (SEQ / 128 - 1) - blockIdx.x;
  int bh = blockIdx.y;
  int b = bh >> 4, h = bh & 15;
  int q0 = qt * 128;
  int tid = threadIdx.x, warp = tid >> 5, lane = tid & 31;
  int gid = lane >> 2, tig = lane & 3;
  int wq = warp * 16;
  const float scl = 0.08838834764831845f;

  const float* base = qkv + (size_t)(b * SEQ) * (3 * DMODEL) + h * 128;

  int r0 = q0 + wq + gid;
  const float* Qp0 = base + (size_t)r0 * (3 * DMODEL);
  const float* Qp1 = Qp0 + (size_t)8 * (3 * DMODEL);
  uint32_t qa[16][4];
  #pragma unroll
  for (int ks = 0; ks < 16; ks++){
    qa[ks][0] = __float_as_uint(__ldg(Qp0 + 8 * ks + tig));
    qa[ks][1] = __float_as_uint(__ldg(Qp1 + 8 * ks + tig));
    qa[ks][2] = __float_as_uint(__ldg(Qp0 + 8 * ks + tig + 4));
    qa[ks][3] = __float_as_uint(__ldg(Qp1 + 8 * ks + tig + 4));
  }

  float O[16][4];
  #pragma unroll
  for (int u = 0; u < 16; u++)
    #pragma unroll
    for (int q = 0; q < 4; q++) O[u][q] = 0.f;
  float m0 = -1e30f, m1 = -1e30f, l0 = 0.f, l1 = 0.f;

  int ntiles = 2 * qt + 2;
  int pf_r  = tid >> 5;
  int pf_d4 = (tid & 31) * 4;
  {
    const float* kg = base + DMODEL + (size_t)pf_r * (3 * DMODEL) + pf_d4;
    #pragma unroll
    for (int it = 0; it < 8; it++){
      uint32_t dk = sbase + ((pf_r + it * 8) * 132 + pf_d4) * 4;
      const float* src = kg + (size_t)(it * 8) * (3 * DMODEL);
      cpa16(dk, src);
      cpa16(dk + AT_TILE_F * 4, src + DMODEL);
    }
    cp_commit();
  }

  for (int kt = 0; kt < ntiles; kt++){
    int buf = kt & 1;
    if (kt + 1 < ntiles){
      int k0n = (kt + 1) * 64;
      const float* kg = base + DMODEL + (size_t)(k0n + pf_r) * (3 * DMODEL) + pf_d4;
      uint32_t db = sbase + ((buf ^ 1) * AT_BUF_F) * 4;
      #pragma unroll
      for (int it = 0; it < 8; it++){
        uint32_t dk = db + ((pf_r + it * 8) * 132 + pf_d4) * 4;
        const float* src = kg + (size_t)(it * 8) * (3 * DMODEL);
        cpa16(dk, src);
        cpa16(dk + AT_TILE_F * 4, src + DMODEL);
      }
      cp_commit();
      cp_wait1();
    } else {
      cp_wait0();
    }
    __syncthreads();

    int k0 = kt * 64;
    bool active = (k0 <= q0 + wq + 15);
    if (active){
      const float* Ks = sm + buf * AT_BUF_F;
      const float* Vs = Ks + AT_TILE_F;

      float s[8][4];
      #pragma unroll
      for (int t = 0; t < 8; t++)
        #pragma unroll
        for (int q = 0; q < 4; q++) s[t][q] = 0.f;
      #pragma unroll
      for (int ks = 0; ks < 16; ks++){
        uint32_t bf[8][2];
        #pragma unroll
        for (int t = 0; t < 8; t++){
          int n0 = 8 * t + gid;
          bf[t][0] = __float_as_uint(Ks[n0 * 132 + 8 * ks + tig]);
          bf[t][1] = __float_as_uint(Ks[n0 * 132 + 8 * ks + tig + 4]);
        }
        #pragma unroll
        for (int t = 0; t < 8; t++)
          mma8(s[t], qa[ks], bf[t]);
      }

      bool dg = (kt >= 2 * qt);
      float mx0 = -1e30f, mx1 = -1e30f;
      #pragma unroll
      for (int t = 0; t < 8; t++){
        float c0 = s[t][0] * scl, c1 = s[t][1] * scl;
        float c2 = s[t][2] * scl, c3 = s[t][3] * scl;
        if (dg){
          int g0 = k0 + 8 * t + 2 * tig;
          if (g0     > r0)     c0 = -1e30f;
          if (g0 + 1 > r0)     c1 = -1e30f;
          if (g0     > r0 + 8) c2 = -1e30f;
          if (g0 + 1 > r0 + 8) c3 = -1e30f;
        }
        s[t][0] = c0; s[t][1] = c1; s[t][2] = c2; s[t][3] = c3;
        mx0 = fmaxf(mx0, fmaxf(c0, c1));
        mx1 = fmaxf(mx1, fmaxf(c2, c3));
      }
      #pragma unroll
      for (int m = 1; m < 4; m <<= 1){
        mx0 = fmaxf(mx0, __shfl_xor_sync(0xffffffffu, mx0, m));
        mx1 = fmaxf(mx1, __shfl_xor_sync(0xffffffffu, mx1, m));
      }
      float mn0 = fmaxf(m0, mx0), mn1 = fmaxf(m1, mx1);
      float cr0 = __expf(m0 - mn0), cr1 = __expf(m1 - mn1);
      m0 = mn0; m1 = mn1;
      float ls0 = 0.f, ls1 = 0.f;
      int lr0 = wq + gid, lr1 = wq + gid + 8;
      #pragma unroll
      for (int t = 0; t < 8; t++){
        float p0 = __expf(s[t][0] - mn0);
        float p1 = __expf(s[t][1] - mn0);
        float p2 = __expf(s[t][2] - mn1);
        float p3 = __expf(s[t][3] - mn1);
        ls0 += p0 + p1; ls1 += p2 + p3;
        float2 w0 = make_float2(tf32r(p0), tf32r(p1));
        float2 w1 = make_float2(tf32r(p2), tf32r(p3));
        *(float2*)&Ps[lr0 * 68 + 8 * t + 2 * tig] = w0;
        *(float2*)&Ps[lr1 * 68 + 8 * t + 2 * tig] = w1;
      }
      #pragma unroll
      for (int m = 1; m < 4; m <<= 1){
        ls0 += __shfl_xor_sync(0xffffffffu, ls0, m);
        ls1 += __shfl_xor_sync(0xffffffffu, ls1, m);
      }
      l0 = l0 * cr0 + ls0;
      l1 = l1 * cr1 + ls1;
      #pragma unroll
      for (int u = 0; u < 16; u++){
        O[u][0] *= cr0; O[u][1] *= cr0;
        O[u][2] *= cr1; O[u][3] *= cr1;
      }
      __syncwarp();

      #pragma unroll
      for (int ks = 0; ks < 8; ks++){
        uint32_t a[4];
        a[0] = __float_as_uint(Ps[lr0 * 68 + 8 * ks + tig]);
        a[1] = __float_as_uint(Ps[lr1 * 68 + 8 * ks + tig]);
        a[2] = __float_as_uint(Ps[lr0 * 68 + 8 * ks + tig + 4]);
        a[3] = __float_as_uint(Ps[lr1 * 68 + 8 * ks + tig + 4]);
        #pragma unroll
        for (int u = 0; u < 16; u++){
          uint32_t bf[2];
          bf[0] = __float_as_uint(Vs[(8 * ks + tig) * 132 + 8 * u + gid]);
          bf[1] = __float_as_uint(Vs[(8 * ks + tig + 4) * 132 + 8 * u + gid]);
          mma8(O[u], a, bf);
        }
      }
      __syncwarp();
    }
    __syncthreads();
  }

  float i0 = 1.0f / l0, i1 = 1.0f / l1;
  float* o0 = av + ((size_t)(b * SEQ) + r0) * DMODEL + h * 128;
  float* o1 = o0 + (size_t)8 * DMODEL;
  #pragma unroll
  for (int u = 0; u < 16; u++){
    float2 v0 = make_float2(tf32r(O[u][0] * i0), tf32r(O[u][1] * i0));
    float2 v1 = make_float2(tf32r(O[u][2] * i1), tf32r(O[u][3] * i1));
    *(float2*)&o0[8 * u + 2 * tig] = v0;
    *(float2*)&o1[8 * u + 2 * tig] = v1;
  }
}

// ---------------- launch ----------------
extern "C" void kernel_launch(void* const* d_in, const int* in_sizes, int n_in,
                              void* d_out, int out_size)
{
  const float* x     = (const float*)d_in[0];
  const float* ln1_g = (const float*)d_in[1];
  const float* ln1_b = (const float*)d_in[2];
  const float* qkv_w = (const float*)d_in[3];
  const float* qkv_b = (const float*)d_in[4];
  const float* out_w = (const float*)d_in[5];
  const float* out_b = (const float*)d_in[6];
  const float* ln2_g = (const float*)d_in[7];
  const float* ln2_b = (const float*)d_in[8];
  const float* w1    = (const float*)d_in[9];
  const float* b1    = (const float*)d_in[10];
  const float* w2    = (const float*)d_in[11];
  const float* b2    = (const float*)d_in[12];
  float* out = (float*)d_out;

  float *h_p, *qkv_p, *av_p, *x1_p, *ffn_p, *wqkv_p, *wout_p, *w1_p, *w2_p;
  cudaGetSymbolAddress((void**)&h_p,    g_h);
  cudaGetSymbolAddress((void**)&qkv_p,  g_qkv);
  cudaGetSymbolAddress((void**)&av_p,   g_av);
  cudaGetSymbolAddress((void**)&x1_p,   g_x1);
  cudaGetSymbolAddress((void**)&ffn_p,  g_ffn);
  cudaGetSymbolAddress((void**)&wqkv_p, g_wqkv_r);
  cudaGetSymbolAddress((void**)&wout_p, g_wout_r);
  cudaGetSymbolAddress((void**)&w1_p,   g_w1_r);
  cudaGetSymbolAddress((void**)&w2_p,   g_w2_r);

  cudaFuncSetAttribute(attn_mma_kernel, cudaFuncAttributeMaxDynamicSharedMemorySize, AT_SMEM);
  cudaFuncSetAttribute(tfgemm2<0,1>, cudaFuncAttributeMaxDynamicSharedMemorySize, G2_SMEM);
  cudaFuncSetAttribute(tfgemm2<1,1>, cudaFuncAttributeMaxDynamicSharedMemorySize, G2_SMEM);

  // single fused weight-round pass
  round_all_kernel<<<RW_TOTAL_F4 / 256, 256>>>(
      (const float4*)qkv_w, (float4*)wqkv_p,
      (const float4*)out_w, (float4*)wout_p,
      (const float4*)w1,    (float4*)w1_p,
      (const float4*)w2,    (float4*)w2_p);

  // 1. LN1 -> rounded
  ln_kernel<<<NTOK, 256>>>(x, ln1_g, ln1_b, h_p);

  // 2. QKV = h @ qkv_w + b (wide N: 128x256 kernel)
  tfgemm2<0,1><<<dim3(24, 32), 256, G2_SMEM>>>(h_p, wqkv_p, qkv_b, nullptr, qkv_p,
                                               NTOK, 3 * DMODEL, DMODEL);

  // 3. mma flash attention (heavy-first) -> rounded
  attn_mma_kernel<<<dim3(SEQ / 128, 2 * NHEAD), 256, AT_SMEM>>>(qkv_p, av_p);

  // 4. x1 = x + av @ out_w + out_b (narrow N: 128x128 occ2 kernel)
  tfgemm<2,0><<<dim3(16, 32), 256>>>(av_p, wout_p, out_b, x, x1_p,
                                     NTOK, DMODEL, DMODEL);

  // 5. LN2 -> rounded
  ln_kernel<<<NTOK, 256>>>(x1_p, ln2_g, ln2_b, h_p);

  // 6. ffn = gelu(h @ w1 + b1) (wide N) -> rounded
  tfgemm2<1,1><<<dim3(32, 32), 256, G2_SMEM>>>(h_p, w1_p, b1, nullptr, ffn_p,
                                               NTOK, FFDIM, DMODEL);

  // 7. out = x1 + ffn @ w2 + b2 (narrow N: 128x128 occ2 kernel)
  tfgemm<2,0><<<dim3(16, 32), 256>>>(ffn_p, w2_p, b2, x1_p, out,
                                     NTOK, DMODEL, FFDIM);
}

// round 8
// speedup vs baseline: 1.7657x; 1.7657x over previous
#include <cuda_runtime.h>
#include <cuda_fp16.h>
#include <math.h>
#include <stdint.h>

#define SEQ     2048
#define DMODEL  2048
#define NHEAD   16
#define FFDIM   8192
#define NTOK    4096
#define LN_EPS  1e-5f

// ---------------- scratch ----------------
__device__ __half g_h   [(size_t)NTOK * DMODEL];
__device__ __half g_qkv [(size_t)NTOK * 3 * DMODEL];
__device__ __half g_av  [(size_t)NTOK * DMODEL];
__device__ float  g_x1  [(size_t)NTOK * DMODEL];
__device__ __half g_ffn [(size_t)NTOK * FFDIM];
__device__ __half g_wqkv[(size_t)3 * DMODEL * DMODEL];  // [N][K]
__device__ __half g_wout[(size_t)DMODEL * DMODEL];
__device__ __half g_w1  [(size_t)FFDIM * DMODEL];
__device__ __half g_w2  [(size_t)DMODEL * FFDIM];

// ---------------- helpers ----------------
__device__ __forceinline__ uint32_t s2u(const void* p){
  uint32_t a;
  asm("{ .reg .u64 t; cvta.to.shared.u64 t, %1; cvt.u32.u64 %0, t; }" : "=r"(a) : "l"(p));
  return a;
}
__device__ __forceinline__ void cpa16(uint32_t dst, const void* src){
  asm volatile("cp.async.cg.shared.global [%0], [%1], 16;" :: "r"(dst), "l"(src));
}
__device__ __forceinline__ void cp_commit(){ asm volatile("cp.async.commit_group;"); }
__device__ __forceinline__ void cp_wait0(){ asm volatile("cp.async.wait_group 0;" ::: "memory"); }
__device__ __forceinline__ void cp_wait1(){ asm volatile("cp.async.wait_group 1;" ::: "memory"); }
__device__ __forceinline__ void mma16(float* c, const uint32_t* a, const uint32_t* b){
  asm volatile("mma.sync.aligned.m16n8k16.row.col.f32.f16.f16.f32 "
    "{%0,%1,%2,%3}, {%4,%5,%6,%7}, {%8,%9}, {%0,%1,%2,%3};"
    : "+f"(c[0]), "+f"(c[1]), "+f"(c[2]), "+f"(c[3])
    : "r"(a[0]), "r"(a[1]), "r"(a[2]), "r"(a[3]), "r"(b[0]), "r"(b[1]));
}
__device__ __forceinline__ void ldmx2t(uint32_t& r0, uint32_t& r1, uint32_t addr){
  asm volatile("ldmatrix.sync.aligned.m8n8.x2.trans.shared.b16 {%0,%1}, [%2];"
    : "=r"(r0), "=r"(r1) : "r"(addr));
}
__device__ __forceinline__ uint32_t packh2(float lo, float hi){
  __half2 h = __floats2half2_rn(lo, hi);
  return *(uint32_t*)&h;
}
__device__ __forceinline__ float gelu_exact(float t){
  return 0.5f * t * (1.0f + erff(t * 0.70710678118654752f));
}

// ---- weight transpose: W[K][N] fp32 -> Wt[N][K] fp16 ----
__global__ __launch_bounds__(256) void wtrans_h(
    const float* __restrict__ W, __half* __restrict__ Wt, int K, int N)
{
  __shared__ float s[32][33];
  int n0 = blockIdx.x * 32, k0 = blockIdx.y * 32;
  int tid = threadIdx.x;
  #pragma unroll
  for (int i = 0; i < 4; i++){
    int idx = tid + i * 256;
    int r = idx >> 5, c = idx & 31;
    s[r][c] = W[(size_t)(k0 + r) * N + n0 + c];
  }
  __syncthreads();
  #pragma unroll
  for (int i = 0; i < 2; i++){
    int c = tid + i * 256;
    int n = c >> 4, k2 = (c & 15) * 2;
    __half2 h = __floats2half2_rn(s[k2][n], s[k2 + 1][n]);
    *(__half2*)&Wt[(size_t)(n0 + n) * K + k0 + k2] = h;
  }
}

// ---- LayerNorm fp32 in -> fp16 out ----
__global__ __launch_bounds__(256) void ln_kernel(
    const float* __restrict__ x, const float* __restrict__ gamma,
    const float* __restrict__ beta, __half* __restrict__ out)
{
  int row = blockIdx.x;
  int tid = threadIdx.x;
  const float4* xr = (const float4*)(x + (size_t)row * DMODEL);
  float4 v0 = xr[tid];
  float4 v1 = xr[tid + 256];
  float s  = v0.x + v0.y + v0.z + v0.w + v1.x + v1.y + v1.z + v1.w;
  float sq = v0.x*v0.x + v0.y*v0.y + v0.z*v0.z + v0.w*v0.w
           + v1.x*v1.x + v1.y*v1.y + v1.z*v1.z + v1.w*v1.w;
  #pragma unroll
  for (int m = 16; m > 0; m >>= 1){
    s  += __shfl_xor_sync(0xffffffffu, s,  m);
    sq += __shfl_xor_sync(0xffffffffu, sq, m);
  }
  __shared__ float red_s[8], red_q[8], bc[2];
  int warp = tid >> 5, lane = tid & 31;
  if (lane == 0){ red_s[warp] = s; red_q[warp] = sq; }
  __syncthreads();
  if (tid == 0){
    float ts = 0.f, tq = 0.f;
    #pragma unroll
    for (int i = 0; i < 8; i++){ ts += red_s[i]; tq += red_q[i]; }
    float mu  = ts * (1.0f / DMODEL);
    float var = tq * (1.0f / DMODEL) - mu * mu;
    bc[0] = mu; bc[1] = rsqrtf(var + LN_EPS);
  }
  __syncthreads();
  float mu = bc[0], rinv = bc[1];
  const float4* gv = (const float4*)gamma;
  const float4* bv = (const float4*)beta;
  float4 g0 = gv[tid], b0 = bv[tid];
  float4 g1 = gv[tid + 256], b1 = bv[tid + 256];
  __half2* ov = (__half2*)(out + (size_t)row * DMODEL);
  ov[2*tid]           = __floats2half2_rn((v0.x-mu)*rinv*g0.x+b0.x, (v0.y-mu)*rinv*g0.y+b0.y);
  ov[2*tid + 1]       = __floats2half2_rn((v0.z-mu)*rinv*g0.z+b0.z, (v0.w-mu)*rinv*g0.w+b0.w);
  ov[512 + 2*tid]     = __floats2half2_rn((v1.x-mu)*rinv*g1.x+b1.x, (v1.y-mu)*rinv*g1.y+b1.y);
  ov[512 + 2*tid + 1] = __floats2half2_rn((v1.z-mu)*rinv*g1.z+b1.z, (v1.w-mu)*rinv*g1.w+b1.w);
}

// ---------------------------------------------------------------------------
// fp16 GEMM wide: C[M,N] = A[M,K] @ Bt[N,K]^T. Tile 128x256, BK=32, occ1,
// 3-stage. 8 warps 2x4, warp 64x64. EPI: 0=bias->half, 1=bias+gelu->half.
// ---------------------------------------------------------------------------
#define HW_AF   (128 * 40)           // halves
#define HW_BF   (256 * 40)
#define HW_STF  (HW_AF + HW_BF)      // 15360 halves
#define HW_SMEM (3 * HW_STF * 2)     // 92160 B

template<int EPI>
__global__ __launch_bounds__(256, 1) void hgemm_w(
    const __half* __restrict__ A, const __half* __restrict__ Bt,
    const float* __restrict__ bias, __half* __restrict__ C, int N, int K)
{
  extern __shared__ __half smh[];
  int tid = threadIdx.x, lane = tid & 31, warp = tid >> 5;
  int bx = blockIdx.x, by = blockIdx.y;
  int wm = (warp >> 2) * 64, wn = (warp & 3) * 64;
  int gid = lane >> 2, tig = lane & 3;

  int a_r = tid >> 2, ko = (tid & 3) * 8;
  const __half* Ag = A + (size_t)(by * 128 + a_r) * K + ko;
  const __half* Bg = Bt + (size_t)(bx * 256 + (tid >> 2)) * K + ko;

  uint32_t smb = s2u(smh);
  uint32_t asd = smb + (a_r * 40 + ko) * 2;
  uint32_t bsd = smb + (HW_AF + (tid >> 2) * 40 + ko) * 2;

  float c[4][8][4];
  #pragma unroll
  for (int mi = 0; mi < 4; mi++)
    #pragma unroll
    for (int ni = 0; ni < 8; ni++)
      #pragma unroll
      for (int q = 0; q < 4; q++) c[mi][ni][q] = 0.f;

  int nk = K >> 5;
  auto issue = [&](int kb, int st){
    uint32_t off = (uint32_t)st * HW_STF * 2;
    cpa16(asd + off,            Ag + (size_t)kb * 32);
    cpa16(asd + off + 64*40*2,  Ag + (size_t)kb * 32 + (size_t)64 * K);
    #pragma unroll
    for (int i = 0; i < 4; i++)
      cpa16(bsd + off + i * 64*40*2, Bg + (size_t)kb * 32 + (size_t)(64 * i) * K);
    cp_commit();
  };
  issue(0, 0);
  if (nk > 1) issue(1, 1);

  for (int kb = 0; kb < nk; kb++){
    int st = kb % 3;
    if (kb + 1 < nk) cp_wait1(); else cp_wait0();
    __syncthreads();
    const __half* As = smh + st * HW_STF;
    const __half* Bs = As + HW_AF;
    #pragma unroll
    for (int ks = 0; ks < 2; ks++){
      uint32_t a[4][4], b[8][2];
      #pragma unroll
      for (int mi = 0; mi < 4; mi++){
        const __half* ab = As + (wm + mi * 16 + gid) * 40 + ks * 16;
        a[mi][0] = *(const uint32_t*)(ab + 2 * tig);
        a[mi][1] = *(const uint32_t*)(ab + 320 + 2 * tig);
        a[mi][2] = *(const uint32_t*)(ab + 2 * tig + 8);
        a[mi][3] = *(const uint32_t*)(ab + 320 + 2 * tig + 8);
      }
      #pragma unroll
      for (int t = 0; t < 8; t++){
        const __half* bb = Bs + (wn + 8 * t + gid) * 40 + ks * 16;
        b[t][0] = *(const uint32_t*)(bb + 2 * tig);
        b[t][1] = *(const uint32_t*)(bb + 2 * tig + 8);
      }
      #pragma unroll
      for (int mi = 0; mi < 4; mi++)
        #pragma unroll
        for (int t = 0; t < 8; t++)
          mma16(c[mi][t], a[mi], b[t]);
    }
    __syncthreads();
    if (kb + 2 < nk) issue(kb + 2, (kb + 2) % 3);
  }

  #pragma unroll
  for (int ni = 0; ni < 8; ni++){
    int col = bx * 256 + wn + ni * 8 + 2 * tig;
    float bb0 = bias[col], bb1 = bias[col + 1];
    #pragma unroll
    for (int mi = 0; mi < 4; mi++){
      int row0 = by * 128 + wm + mi * 16 + gid;
      float v00 = c[mi][ni][0] + bb0, v01 = c[mi][ni][1] + bb1;
      float v10 = c[mi][ni][2] + bb0, v11 = c[mi][ni][3] + bb1;
      if (EPI == 1){
        v00 = gelu_exact(v00); v01 = gelu_exact(v01);
        v10 = gelu_exact(v10); v11 = gelu_exact(v11);
      }
      *(__half2*)&C[(size_t)row0 * N + col]       = __floats2half2_rn(v00, v01);
      *(__half2*)&C[(size_t)(row0 + 8) * N + col] = __floats2half2_rn(v10, v11);
    }
  }
}

// ---------------------------------------------------------------------------
// fp16 GEMM narrow: tile 128x128, occ2, 2-stage. warp 64x32.
// EPI=2: bias + residual(fp32) -> fp32 out.
// ---------------------------------------------------------------------------
__global__ __launch_bounds__(256, 2) void hgemm_n(
    const __half* __restrict__ A, const __half* __restrict__ Bt,
    const float* __restrict__ bias, const float* __restrict__ res,
    float* __restrict__ C, int N, int K)
{
  __shared__ __half As[2][128 * 40];
  __shared__ __half Bs[2][128 * 40];

  int tid = threadIdx.x, lane = tid & 31, warp = tid >> 5;
  int bx = blockIdx.x, by = blockIdx.y;
  int wm = (warp >> 2) * 64, wn = (warp & 3) * 32;
  int gid = lane >> 2, tig = lane & 3;

  int a_r = tid >> 2, ko = (tid & 3) * 8;
  const __half* Ag = A + (size_t)(by * 128 + a_r) * K + ko;
  const __half* Bg = Bt + (size_t)(bx * 128 + a_r) * K + ko;
  uint32_t asd = s2u(&As[0][a_r * 40 + ko]);
  uint32_t bsd = s2u(&Bs[0][a_r * 40 + ko]);
  const uint32_t stB = 128 * 40 * 2;

  float c[4][4][4];
  #pragma unroll
  for (int mi = 0; mi < 4; mi++)
    #pragma unroll
    for (int ni = 0; ni < 4; ni++)
      #pragma unroll
      for (int q = 0; q < 4; q++) c[mi][ni][q] = 0.f;

  int nk = K >> 5;
  auto issue = [&](int kb, int st){
    uint32_t off = st ? stB : 0;
    cpa16(asd + off,           Ag + (size_t)kb * 32);
    cpa16(asd + off + 64*40*2, Ag + (size_t)kb * 32 + (size_t)64 * K);
    cpa16(bsd + off,           Bg + (size_t)kb * 32);
    cpa16(bsd + off + 64*40*2, Bg + (size_t)kb * 32 + (size_t)64 * K);
    cp_commit();
  };
  issue(0, 0);

  for (int kb = 0; kb < nk; kb++){
    int st = kb & 1;
    cp_wait0();
    __syncthreads();
    if (kb + 1 < nk) issue(kb + 1, st ^ 1);
    const __half* as = As[st];
    const __half* bs = Bs[st];
    #pragma unroll
    for (int ks = 0; ks < 2; ks++){
      uint32_t a[4][4], b[4][2];
      #pragma unroll
      for (int mi = 0; mi < 4; mi++){
        const __half* ab = as + (wm + mi * 16 + gid) * 40 + ks * 16;
        a[mi][0] = *(const uint32_t*)(ab + 2 * tig);
        a[mi][1] = *(const uint32_t*)(ab + 320 + 2 * tig);
        a[mi][2] = *(const uint32_t*)(ab + 2 * tig + 8);
        a[mi][3] = *(const uint32_t*)(ab + 320 + 2 * tig + 8);
      }
      #pragma unroll
      for (int t = 0; t < 4; t++){
        const __half* bb = bs + (wn + 8 * t + gid) * 40 + ks * 16;
        b[t][0] = *(const uint32_t*)(bb + 2 * tig);
        b[t][1] = *(const uint32_t*)(bb + 2 * tig + 8);
      }
      #pragma unroll
      for (int mi = 0; mi < 4; mi++)
        #pragma unroll
        for (int t = 0; t < 4; t++)
          mma16(c[mi][t], a[mi], b[t]);
    }
    __syncthreads();
  }

  #pragma unroll
  for (int ni = 0; ni < 4; ni++){
    int col = bx * 128 + wn + ni * 8 + 2 * tig;
    float bb0 = bias[col], bb1 = bias[col + 1];
    #pragma unroll
    for (int mi = 0; mi < 4; mi++){
      int row0 = by * 128 + wm + mi * 16 + gid;
      float2 r0 = *(const float2*)&res[(size_t)row0 * N + col];
      float2 r1 = *(const float2*)&res[(size_t)(row0 + 8) * N + col];
      float2 v0 = make_float2(c[mi][ni][0] + bb0 + r0.x, c[mi][ni][1] + bb1 + r0.y);
      float2 v1 = make_float2(c[mi][ni][2] + bb0 + r1.x, c[mi][ni][3] + bb1 + r1.y);
      *(float2*)&C[(size_t)row0 * N + col]       = v0;
      *(float2*)&C[(size_t)(row0 + 8) * N + col] = v1;
    }
  }
}

// ---------------------------------------------------------------------------
// fp16 mma flash attention. CTA: 128 queries x (b,h). 8 warps x 16 q-rows.
// K-tiles 64, double-buffered K/V (stride 136 halves). P feeds PV directly
// from S accumulators; V B-frags via ldmatrix.trans.
// ---------------------------------------------------------------------------
#define AT_TF   (64 * 136)           // halves per tile
#define AT_STF  (2 * AT_TF)          // K+V stage
#define AT_SMEM (2 * AT_STF * 2)     // 69632 B

__global__ __launch_bounds__(256, 1) void attn_h(
    const __half* __restrict__ qkv, __half* __restrict__ av)
{
  extern __shared__ __half smh[];
  uint32_t sbase = s2u(smh);

  int qt = blockIdx.x, bh = blockIdx.y;
  int b = bh >> 4, h = bh & 15;
  int q0 = qt * 128;
  int tid = threadIdx.x, warp = tid >> 5, lane = tid & 31;
  int gid = lane >> 2, tig = lane & 3;
  int wq = warp * 16;
  const float scl = 0.08838834764831845f;

  const __half* base = qkv + (size_t)(b * SEQ) * (3 * DMODEL) + h * 128;

  int r0 = q0 + wq + gid;
  const __half* Qp0 = base + (size_t)r0 * (3 * DMODEL);
  const __half* Qp1 = Qp0 + (size_t)8 * (3 * DMODEL);
  uint32_t qa[8][4];
  #pragma unroll
  for (int j = 0; j < 8; j++){
    qa[j][0] = *(const uint32_t*)(Qp0 + 16 * j + 2 * tig);
    qa[j][1] = *(const uint32_t*)(Qp1 + 16 * j + 2 * tig);
    qa[j][2] = *(const uint32_t*)(Qp0 + 16 * j + 2 * tig + 8);
    qa[j][3] = *(const uint32_t*)(Qp1 + 16 * j + 2 * tig + 8);
  }

  float O[16][4];
  #pragma unroll
  for (int u = 0; u < 16; u++)
    #pragma unroll
    for (int q = 0; q < 4; q++) O[u][q] = 0.f;
  float m0 = -1e30f, m1 = -1e30f, l0 = 0.f, l1 = 0.f;

  int ntiles = 2 * qt + 2;
  int pf_r = tid >> 4, pf_d = (tid & 15) * 8;   // 16 rows per pass, 4 passes

  auto prefetch = [&](int kt, int buf){
    uint32_t db = sbase + (uint32_t)buf * AT_STF * 2;
    const __half* kg = base + DMODEL + (size_t)(kt * 64 + pf_r) * (3 * DMODEL) + pf_d;
    #pragma unroll
    for (int it = 0; it < 4; it++){
      uint32_t dk = db + ((pf_r + it * 16) * 136 + pf_d) * 2;
      const __half* src = kg + (size_t)(it * 16) * (3 * DMODEL);
      cpa16(dk, src);                              // K
      cpa16(dk + AT_TF * 2, src + DMODEL);         // V
    }
    cp_commit();
  };
  prefetch(0, 0);

  for (int kt = 0; kt < ntiles; kt++){
    int buf = kt & 1;
    if (kt + 1 < ntiles){ prefetch(kt + 1, buf ^ 1); cp_wait1(); }
    else cp_wait0();
    __syncthreads();

    int k0 = kt * 64;
    if (k0 <= q0 + wq + 15){
      const __half* Ks = smh + buf * AT_STF;
      const __half* Vs = Ks + AT_TF;

      // S = Q @ K^T
      float s[8][4];
      #pragma unroll
      for (int t = 0; t < 8; t++)
        #pragma unroll
        for (int q = 0; q < 4; q++) s[t][q] = 0.f;
      #pragma unroll
      for (int j = 0; j < 8; j++){
        #pragma unroll
        for (int t = 0; t < 8; t++){
          const __half* bb = Ks + (8 * t + gid) * 136 + 16 * j;
          uint32_t b0 = *(const uint32_t*)(bb + 2 * tig);
          uint32_t b1 = *(const uint32_t*)(bb + 2 * tig + 8);
          uint32_t bf[2] = {b0, b1};
          mma16(s[t], qa[j], bf);
        }
      }

      // scale + causal mask + online softmax
      bool dg = (kt >= 2 * qt);
      float mx0 = -1e30f, mx1 = -1e30f;
      #pragma unroll
      for (int t = 0; t < 8; t++){
        float c0 = s[t][0] * scl, c1 = s[t][1] * scl;
        float c2 = s[t][2] * scl, c3 = s[t][3] * scl;
        if (dg){
          int g0 = k0 + 8 * t + 2 * tig;
          if (g0     > r0)     c0 = -1e30f;
          if (g0 + 1 > r0)     c1 = -1e30f;
          if (g0     > r0 + 8) c2 = -1e30f;
          if (g0 + 1 > r0 + 8) c3 = -1e30f;
        }
        s[t][0] = c0; s[t][1] = c1; s[t][2] = c2; s[t][3] = c3;
        mx0 = fmaxf(mx0, fmaxf(c0, c1));
        mx1 = fmaxf(mx1, fmaxf(c2, c3));
      }
      #pragma unroll
      for (int m = 1; m < 4; m <<= 1){
        mx0 = fmaxf(mx0, __shfl_xor_sync(0xffffffffu, mx0, m));
        mx1 = fmaxf(mx1, __shfl_xor_sync(0xffffffffu, mx1, m));
      }
      float mn0 = fmaxf(m0, mx0), mn1 = fmaxf(m1, mx1);
      float cr0 = __expf(m0 - mn0), cr1 = __expf(m1 - mn1);
      m0 = mn0; m1 = mn1;
      float ls0 = 0.f, ls1 = 0.f;
      #pragma unroll
      for (int t = 0; t < 8; t++){
        s[t][0] = __expf(s[t][0] - mn0);
        s[t][1] = __expf(s[t][1] - mn0);
        s[t][2] = __expf(s[t][2] - mn1);
        s[t][3] = __expf(s[t][3] - mn1);
        ls0 += s[t][0] + s[t][1];
        ls1 += s[t][2] + s[t][3];
      }
      #pragma unroll
      for (int m = 1; m < 4; m <<= 1){
        ls0 += __shfl_xor_sync(0xffffffffu, ls0, m);
        ls1 += __shfl_xor_sync(0xffffffffu, ls1, m);
      }
      l0 = l0 * cr0 + ls0;
      l1 = l1 * cr1 + ls1;
      #pragma unroll
      for (int u = 0; u < 16; u++){
        O[u][0] *= cr0; O[u][1] *= cr0;
        O[u][2] *= cr1; O[u][3] *= cr1;
      }

      // O += P @ V  (P direct from S accumulators; V via ldmatrix.trans)
      #pragma unroll
      for (int j2 = 0; j2 < 4; j2++){
        uint32_t pa[4];
        pa[0] = packh2(s[2*j2][0],   s[2*j2][1]);
        pa[1] = packh2(s[2*j2][2],   s[2*j2][3]);
        pa[2] = packh2(s[2*j2+1][0], s[2*j2+1][1]);
        pa[3] = packh2(s[2*j2+1][2], s[2*j2+1][3]);
        uint32_t vrow = sbase + (uint32_t)buf * AT_STF * 2 + AT_TF * 2
                      + ((16 * j2 + (lane & 15)) * 136) * 2;
        #pragma unroll
        for (int u = 0; u < 16; u++){
          uint32_t b0, b1;
          ldmx2t(b0, b1, vrow + 16 * u);
          uint32_t bf[2] = {b0, b1};
          mma16(O[u], pa, bf);
        }
      }
    }
    __syncthreads();
  }

  float i0 = 1.0f / l0, i1 = 1.0f / l1;
  __half* o0 = av + ((size_t)(b * SEQ) + r0) * DMODEL + h * 128;
  __half* o1 = o0 + (size_t)8 * DMODEL;
  #pragma unroll
  for (int u = 0; u < 16; u++){
    *(__half2*)&o0[8 * u + 2 * tig] = __floats2half2_rn(O[u][0] * i0, O[u][1] * i0);
    *(__half2*)&o1[8 * u + 2 * tig] = __floats2half2_rn(O[u][2] * i1, O[u][3] * i1);
  }
}

// ---------------- launch ----------------
extern "C" void kernel_launch(void* const* d_in, const int* in_sizes, int n_in,
                              void* d_out, int out_size)
{
  const float* x     = (const float*)d_in[0];
  const float* ln1_g = (const float*)d_in[1];
  const float* ln1_b = (const float*)d_in[2];
  const float* qkv_w = (const float*)d_in[3];
  const float* qkv_b = (const float*)d_in[4];
  const float* out_w = (const float*)d_in[5];
  const float* out_b = (const float*)d_in[6];
  const float* ln2_g = (const float*)d_in[7];
  const float* ln2_b = (const float*)d_in[8];
  const float* w1    = (const float*)d_in[9];
  const float* b1    = (const float*)d_in[10];
  const float* w2    = (const float*)d_in[11];
  const float* b2    = (const float*)d_in[12];
  float* out = (float*)d_out;

  __half *h_p, *qkv_p, *av_p, *ffn_p, *wqkv_p, *wout_p, *w1_p, *w2_p;
  float *x1_p;
  cudaGetSymbolAddress((void**)&h_p,    g_h);
  cudaGetSymbolAddress((void**)&qkv_p,  g_qkv);
  cudaGetSymbolAddress((void**)&av_p,   g_av);
  cudaGetSymbolAddress((void**)&x1_p,   g_x1);
  cudaGetSymbolAddress((void**)&ffn_p,  g_ffn);
  cudaGetSymbolAddress((void**)&wqkv_p, g_wqkv);
  cudaGetSymbolAddress((void**)&wout_p, g_wout);
  cudaGetSymbolAddress((void**)&w1_p,   g_w1);
  cudaGetSymbolAddress((void**)&w2_p,   g_w2);

  cudaFuncSetAttribute(attn_h, cudaFuncAttributeMaxDynamicSharedMemorySize, AT_SMEM);
  cudaFuncSetAttribute(hgemm_w<0>, cudaFuncAttributeMaxDynamicSharedMemorySize, HW_SMEM);
  cudaFuncSetAttribute(hgemm_w<1>, cudaFuncAttributeMaxDynamicSharedMemorySize, HW_SMEM);

  // weight transposes fp32[K][N] -> fp16[N][K]
  wtrans_h<<<dim3(192, 64), 256>>>(qkv_w, wqkv_p, DMODEL, 3 * DMODEL);
  wtrans_h<<<dim3(64, 64),  256>>>(out_w, wout_p, DMODEL, DMODEL);
  wtrans_h<<<dim3(256, 64), 256>>>(w1, w1_p, DMODEL, FFDIM);
  wtrans_h<<<dim3(64, 256), 256>>>(w2, w2_p, FFDIM, DMODEL);

  // 1. LN1 -> fp16
  ln_kernel<<<NTOK, 256>>>(x, ln1_g, ln1_b, h_p);

  // 2. QKV (fp16 out)
  hgemm_w<0><<<dim3(24, 32), 256, HW_SMEM>>>(h_p, wqkv_p, qkv_b, qkv_p,
                                             3 * DMODEL, DMODEL);

  // 3. fp16 flash attention
  attn_h<<<dim3(SEQ / 128, 2 * NHEAD), 256, AT_SMEM>>>(qkv_p, av_p);

  // 4. x1 = x + av @ out_w + out_b (fp32 out)
  hgemm_n<<<dim3(16, 32), 256>>>(av_p, wout_p, out_b, x, x1_p, DMODEL, DMODEL);

  // 5. LN2 -> fp16
  ln_kernel<<<NTOK, 256>>>(x1_p, ln2_g, ln2_b, h_p);

  // 6. ffn = gelu(h @ w1 + b1) (fp16 out)
  hgemm_w<1><<<dim3(32, 32), 256, HW_SMEM>>>(h_p, w1_p, b1, ffn_p, FFDIM, DMODEL);

  // 7. out = x1 + ffn @ w2 + b2 (fp32 out)
  hgemm_n<<<dim3(16, 32), 256>>>(ffn_p, w2_p, b2, x1_p, out, DMODEL, FFDIM);
}

// round 9
// speedup vs baseline: 1.7790x; 1.0075x over previous
#include <cuda_runtime.h>
#include <cuda_fp16.h>
#include <math.h>
#include <stdint.h>

#define SEQ     2048
#define DMODEL  2048
#define NHEAD   16
#define FFDIM   8192
#define NTOK    4096
#define LN_EPS  1e-5f

// ---------------- scratch ----------------
__device__ __half g_h   [(size_t)NTOK * DMODEL];
__device__ __half g_qkv [(size_t)NTOK * 3 * DMODEL];
__device__ __half g_av  [(size_t)NTOK * DMODEL];
__device__ float  g_x1  [(size_t)NTOK * DMODEL];
__device__ __half g_ffn [(size_t)NTOK * FFDIM];
__device__ __half g_wqkv[(size_t)3 * DMODEL * DMODEL];  // [N][K]
__device__ __half g_wout[(size_t)DMODEL * DMODEL];
__device__ __half g_w1  [(size_t)FFDIM * DMODEL];
__device__ __half g_w2  [(size_t)DMODEL * FFDIM];

// ---------------- helpers ----------------
__device__ __forceinline__ uint32_t s2u(const void* p){
  uint32_t a;
  asm("{ .reg .u64 t; cvta.to.shared.u64 t, %1; cvt.u32.u64 %0, t; }" : "=r"(a) : "l"(p));
  return a;
}
__device__ __forceinline__ void cpa16(uint32_t dst, const void* src){
  asm volatile("cp.async.cg.shared.global [%0], [%1], 16;" :: "r"(dst), "l"(src));
}
__device__ __forceinline__ void cp_commit(){ asm volatile("cp.async.commit_group;"); }
__device__ __forceinline__ void cp_wait0(){ asm volatile("cp.async.wait_group 0;" ::: "memory"); }
__device__ __forceinline__ void cp_wait1(){ asm volatile("cp.async.wait_group 1;" ::: "memory"); }
__device__ __forceinline__ void mma16(float* c, const uint32_t* a, const uint32_t* b){
  asm volatile("mma.sync.aligned.m16n8k16.row.col.f32.f16.f16.f32 "
    "{%0,%1,%2,%3}, {%4,%5,%6,%7}, {%8,%9}, {%0,%1,%2,%3};"
    : "+f"(c[0]), "+f"(c[1]), "+f"(c[2]), "+f"(c[3])
    : "r"(a[0]), "r"(a[1]), "r"(a[2]), "r"(a[3]), "r"(b[0]), "r"(b[1]));
}
__device__ __forceinline__ void ldmx2t(uint32_t& r0, uint32_t& r1, uint32_t addr){
  asm volatile("ldmatrix.sync.aligned.m8n8.x2.trans.shared.b16 {%0,%1}, [%2];"
    : "=r"(r0), "=r"(r1) : "r"(addr));
}
__device__ __forceinline__ uint32_t packh2(float lo, float hi){
  __half2 h = __floats2half2_rn(lo, hi);
  return *(uint32_t*)&h;
}
__device__ __forceinline__ float gelu_exact(float t){
  return 0.5f * t * (1.0f + erff(t * 0.70710678118654752f));
}

// ---- fused weight transpose: all 4 matrices, W[K][N] fp32 -> Wt[N][K] fp16 ----
// tiles: qkv 192x64=12288, out 64x64=4096, w1 256x64=16384, w2 64x256=16384
#define WT_TILES 49152
__global__ __launch_bounds__(256) void wtrans_all(
    const float* __restrict__ qkv_w, __half* __restrict__ o_qkv,
    const float* __restrict__ out_w, __half* __restrict__ o_out,
    const float* __restrict__ w1,    __half* __restrict__ o_w1,
    const float* __restrict__ w2,    __half* __restrict__ o_w2)
{
  __shared__ float s[32][33];
  int bid = blockIdx.x;
  const float* W; __half* Wt; int K, N, nx, tile;
  if (bid < 12288){ W = qkv_w; Wt = o_qkv; K = 2048; N = 6144; nx = 192; tile = bid; }
  else if (bid < 16384){ W = out_w; Wt = o_out; K = 2048; N = 2048; nx = 64; tile = bid - 12288; }
  else if (bid < 32768){ W = w1; Wt = o_w1; K = 2048; N = 8192; nx = 256; tile = bid - 16384; }
  else { W = w2; Wt = o_w2; K = 8192; N = 2048; nx = 64; tile = bid - 32768; }
  int n0 = (tile % nx) * 32, k0 = (tile / nx) * 32;
  int tid = threadIdx.x;
  #pragma unroll
  for (int i = 0; i < 4; i++){
    int idx = tid + i * 256;
    int r = idx >> 5, c = idx & 31;
    s[r][c] = W[(size_t)(k0 + r) * N + n0 + c];
  }
  __syncthreads();
  #pragma unroll
  for (int i = 0; i < 2; i++){
    int c = tid + i * 256;
    int n = c >> 4, k2 = (c & 15) * 2;
    __half2 h = __floats2half2_rn(s[k2][n], s[k2 + 1][n]);
    *(__half2*)&Wt[(size_t)(n0 + n) * K + k0 + k2] = h;
  }
}

// ---- LayerNorm fp32 in -> fp16 out ----
__global__ __launch_bounds__(256) void ln_kernel(
    const float* __restrict__ x, const float* __restrict__ gamma,
    const float* __restrict__ beta, __half* __restrict__ out)
{
  int row = blockIdx.x;
  int tid = threadIdx.x;
  const float4* xr = (const float4*)(x + (size_t)row * DMODEL);
  float4 v0 = xr[tid];
  float4 v1 = xr[tid + 256];
  float s  = v0.x + v0.y + v0.z + v0.w + v1.x + v1.y + v1.z + v1.w;
  float sq = v0.x*v0.x + v0.y*v0.y + v0.z*v0.z + v0.w*v0.w
           + v1.x*v1.x + v1.y*v1.y + v1.z*v1.z + v1.w*v1.w;
  #pragma unroll
  for (int m = 16; m > 0; m >>= 1){
    s  += __shfl_xor_sync(0xffffffffu, s,  m);
    sq += __shfl_xor_sync(0xffffffffu, sq, m);
  }
  __shared__ float red_s[8], red_q[8], bc[2];
  int warp = tid >> 5, lane = tid & 31;
  if (lane == 0){ red_s[warp] = s; red_q[warp] = sq; }
  __syncthreads();
  if (tid == 0){
    float ts = 0.f, tq = 0.f;
    #pragma unroll
    for (int i = 0; i < 8; i++){ ts += red_s[i]; tq += red_q[i]; }
    float mu  = ts * (1.0f / DMODEL);
    float var = tq * (1.0f / DMODEL) - mu * mu;
    bc[0] = mu; bc[1] = rsqrtf(var + LN_EPS);
  }
  __syncthreads();
  float mu = bc[0], rinv = bc[1];
  const float4* gv = (const float4*)gamma;
  const float4* bv = (const float4*)beta;
  float4 g0 = gv[tid], b0 = bv[tid];
  float4 g1 = gv[tid + 256], b1 = bv[tid + 256];
  __half2* ov = (__half2*)(out + (size_t)row * DMODEL);
  ov[2*tid]           = __floats2half2_rn((v0.x-mu)*rinv*g0.x+b0.x, (v0.y-mu)*rinv*g0.y+b0.y);
  ov[2*tid + 1]       = __floats2half2_rn((v0.z-mu)*rinv*g0.z+b0.z, (v0.w-mu)*rinv*g0.w+b0.w);
  ov[512 + 2*tid]     = __floats2half2_rn((v1.x-mu)*rinv*g1.x+b1.x, (v1.y-mu)*rinv*g1.y+b1.y);
  ov[512 + 2*tid + 1] = __floats2half2_rn((v1.z-mu)*rinv*g1.z+b1.z, (v1.w-mu)*rinv*g1.w+b1.w);
}

// ---------------------------------------------------------------------------
// fp16 GEMM wide: tile 128x256, BK=32, occ1, 3-stage. EPI: 0=bias, 1=bias+gelu.
// ---------------------------------------------------------------------------
#define HW_AF   (128 * 40)
#define HW_BF   (256 * 40)
#define HW_STF  (HW_AF + HW_BF)
#define HW_SMEM (3 * HW_STF * 2)

template<int EPI>
__global__ __launch_bounds__(256, 1) void hgemm_w(
    const __half* __restrict__ A, const __half* __restrict__ Bt,
    const float* __restrict__ bias, __half* __restrict__ C, int N, int K)
{
  extern __shared__ __half smh[];
  int tid = threadIdx.x, lane = tid & 31, warp = tid >> 5;
  int bx = blockIdx.x, by = blockIdx.y;
  int wm = (warp >> 2) * 64, wn = (warp & 3) * 64;
  int gid = lane >> 2, tig = lane & 3;

  int a_r = tid >> 2, ko = (tid & 3) * 8;
  const __half* Ag = A + (size_t)(by * 128 + a_r) * K + ko;
  const __half* Bg = Bt + (size_t)(bx * 256 + a_r) * K + ko;

  uint32_t smb = s2u(smh);
  uint32_t asd = smb + (a_r * 40 + ko) * 2;
  uint32_t bsd = smb + (HW_AF + a_r * 40 + ko) * 2;

  float c[4][8][4];
  #pragma unroll
  for (int mi = 0; mi < 4; mi++)
    #pragma unroll
    for (int ni = 0; ni < 8; ni++)
      #pragma unroll
      for (int q = 0; q < 4; q++) c[mi][ni][q] = 0.f;

  int nk = K >> 5;
  auto issue = [&](int kb, int st){
    uint32_t off = (uint32_t)st * HW_STF * 2;
    cpa16(asd + off,            Ag + (size_t)kb * 32);
    cpa16(asd + off + 64*40*2,  Ag + (size_t)kb * 32 + (size_t)64 * K);
    #pragma unroll
    for (int i = 0; i < 4; i++)
      cpa16(bsd + off + i * 64*40*2, Bg + (size_t)kb * 32 + (size_t)(64 * i) * K);
    cp_commit();
  };
  issue(0, 0);
  if (nk > 1) issue(1, 1);

  for (int kb = 0; kb < nk; kb++){
    int st = kb % 3;
    if (kb + 1 < nk) cp_wait1(); else cp_wait0();
    __syncthreads();
    const __half* As = smh + st * HW_STF;
    const __half* Bs = As + HW_AF;
    #pragma unroll
    for (int ks = 0; ks < 2; ks++){
      uint32_t a[4][4], b[8][2];
      #pragma unroll
      for (int mi = 0; mi < 4; mi++){
        const __half* ab = As + (wm + mi * 16 + gid) * 40 + ks * 16;
        a[mi][0] = *(const uint32_t*)(ab + 2 * tig);
        a[mi][1] = *(const uint32_t*)(ab + 320 + 2 * tig);
        a[mi][2] = *(const uint32_t*)(ab + 2 * tig + 8);
        a[mi][3] = *(const uint32_t*)(ab + 320 + 2 * tig + 8);
      }
      #pragma unroll
      for (int t = 0; t < 8; t++){
        const __half* bb = Bs + (wn + 8 * t + gid) * 40 + ks * 16;
        b[t][0] = *(const uint32_t*)(bb + 2 * tig);
        b[t][1] = *(const uint32_t*)(bb + 2 * tig + 8);
      }
      #pragma unroll
      for (int mi = 0; mi < 4; mi++)
        #pragma unroll
        for (int t = 0; t < 8; t++)
          mma16(c[mi][t], a[mi], b[t]);
    }
    __syncthreads();
    if (kb + 2 < nk) issue(kb + 2, (kb + 2) % 3);
  }

  #pragma unroll
  for (int ni = 0; ni < 8; ni++){
    int col = bx * 256 + wn + ni * 8 + 2 * tig;
    float bb0 = bias[col], bb1 = bias[col + 1];
    #pragma unroll
    for (int mi = 0; mi < 4; mi++){
      int row0 = by * 128 + wm + mi * 16 + gid;
      float v00 = c[mi][ni][0] + bb0, v01 = c[mi][ni][1] + bb1;
      float v10 = c[mi][ni][2] + bb0, v11 = c[mi][ni][3] + bb1;
      if (EPI == 1){
        v00 = gelu_exact(v00); v01 = gelu_exact(v01);
        v10 = gelu_exact(v10); v11 = gelu_exact(v11);
      }
      *(__half2*)&C[(size_t)row0 * N + col]       = __floats2half2_rn(v00, v01);
      *(__half2*)&C[(size_t)(row0 + 8) * N + col] = __floats2half2_rn(v10, v11);
    }
  }
}

// ---------------------------------------------------------------------------
// fp16 GEMM narrow: tile 128x128, occ2, 2-stage. bias + residual -> fp32.
// ---------------------------------------------------------------------------
__global__ __launch_bounds__(256, 2) void hgemm_n(
    const __half* __restrict__ A, const __half* __restrict__ Bt,
    const float* __restrict__ bias, const float* __restrict__ res,
    float* __restrict__ C, int N, int K)
{
  __shared__ __half As[2][128 * 40];
  __shared__ __half Bs[2][128 * 40];

  int tid = threadIdx.x, lane = tid & 31, warp = tid >> 5;
  int bx = blockIdx.x, by = blockIdx.y;
  int wm = (warp >> 2) * 64, wn = (warp & 3) * 32;
  int gid = lane >> 2, tig = lane & 3;

  int a_r = tid >> 2, ko = (tid & 3) * 8;
  const __half* Ag = A + (size_t)(by * 128 + a_r) * K + ko;
  const __half* Bg = Bt + (size_t)(bx * 128 + a_r) * K + ko;
  uint32_t asd = s2u(&As[0][a_r * 40 + ko]);
  uint32_t bsd = s2u(&Bs[0][a_r * 40 + ko]);
  const uint32_t stB = 128 * 40 * 2;

  float c[4][4][4];
  #pragma unroll
  for (int mi = 0; mi < 4; mi++)
    #pragma unroll
    for (int ni = 0; ni < 4; ni++)
      #pragma unroll
      for (int q = 0; q < 4; q++) c[mi][ni][q] = 0.f;

  int nk = K >> 5;
  auto issue = [&](int kb, int st){
    uint32_t off = st ? stB : 0;
    cpa16(asd + off,           Ag + (size_t)kb * 32);
    cpa16(asd + off + 64*40*2, Ag + (size_t)kb * 32 + (size_t)64 * K);
    cpa16(bsd + off,           Bg + (size_t)kb * 32);
    cpa16(bsd + off + 64*40*2, Bg + (size_t)kb * 32 + (size_t)64 * K);
    cp_commit();
  };
  issue(0, 0);

  for (int kb = 0; kb < nk; kb++){
    int st = kb & 1;
    cp_wait0();
    __syncthreads();
    if (kb + 1 < nk) issue(kb + 1, st ^ 1);
    const __half* as = As[st];
    const __half* bs = Bs[st];
    #pragma unroll
    for (int ks = 0; ks < 2; ks++){
      uint32_t a[4][4], b[4][2];
      #pragma unroll
      for (int mi = 0; mi < 4; mi++){
        const __half* ab = as + (wm + mi * 16 + gid) * 40 + ks * 16;
        a[mi][0] = *(const uint32_t*)(ab + 2 * tig);
        a[mi][1] = *(const uint32_t*)(ab + 320 + 2 * tig);
        a[mi][2] = *(const uint32_t*)(ab + 2 * tig + 8);
        a[mi][3] = *(const uint32_t*)(ab + 320 + 2 * tig + 8);
      }
      #pragma unroll
      for (int t = 0; t < 4; t++){
        const __half* bb = bs + (wn + 8 * t + gid) * 40 + ks * 16;
        b[t][0] = *(const uint32_t*)(bb + 2 * tig);
        b[t][1] = *(const uint32_t*)(bb + 2 * tig + 8);
      }
      #pragma unroll
      for (int mi = 0; mi < 4; mi++)
        #pragma unroll
        for (int t = 0; t < 4; t++)
          mma16(c[mi][t], a[mi], b[t]);
    }
    __syncthreads();
  }

  #pragma unroll
  for (int ni = 0; ni < 4; ni++){
    int col = bx * 128 + wn + ni * 8 + 2 * tig;
    float bb0 = bias[col], bb1 = bias[col + 1];
    #pragma unroll
    for (int mi = 0; mi < 4; mi++){
      int row0 = by * 128 + wm + mi * 16 + gid;
      float2 r0 = *(const float2*)&res[(size_t)row0 * N + col];
      float2 r1 = *(const float2*)&res[(size_t)(row0 + 8) * N + col];
      float2 v0 = make_float2(c[mi][ni][0] + bb0 + r0.x, c[mi][ni][1] + bb1 + r0.y);
      float2 v1 = make_float2(c[mi][ni][2] + bb0 + r1.x, c[mi][ni][3] + bb1 + r1.y);
      *(float2*)&C[(size_t)row0 * N + col]       = v0;
      *(float2*)&C[(size_t)(row0 + 8) * N + col] = v1;
    }
  }
}

// ---------------------------------------------------------------------------
// fp16 mma flash attention. CTA: 128 queries x (b,h). K-tile 128 (double-
// buffered K/V, 139KB smem). P direct from S accumulators; V via ldmatrix.
// ---------------------------------------------------------------------------
#define AT_TF   (128 * 136)          // halves per K (or V) tile
#define AT_STF  (2 * AT_TF)
#define AT_SMEM (2 * AT_STF * 2)     // 139264 B

__global__ __launch_bounds__(256, 1) void attn_h(
    const __half* __restrict__ qkv, __half* __restrict__ av)
{
  extern __shared__ __half smh[];
  uint32_t sbase = s2u(smh);

  int qt = blockIdx.x, bh = blockIdx.y;
  int b = bh >> 4, h = bh & 15;
  int q0 = qt * 128;
  int tid = threadIdx.x, warp = tid >> 5, lane = tid & 31;
  int gid = lane >> 2, tig = lane & 3;
  int wq = warp * 16;
  const float scl = 0.08838834764831845f;

  const __half* base = qkv + (size_t)(b * SEQ) * (3 * DMODEL) + h * 128;

  int r0 = q0 + wq + gid;
  const __half* Qp0 = base + (size_t)r0 * (3 * DMODEL);
  const __half* Qp1 = Qp0 + (size_t)8 * (3 * DMODEL);
  uint32_t qa[8][4];
  #pragma unroll
  for (int j = 0; j < 8; j++){
    qa[j][0] = *(const uint32_t*)(Qp0 + 16 * j + 2 * tig);
    qa[j][1] = *(const uint32_t*)(Qp1 + 16 * j + 2 * tig);
    qa[j][2] = *(const uint32_t*)(Qp0 + 16 * j + 2 * tig + 8);
    qa[j][3] = *(const uint32_t*)(Qp1 + 16 * j + 2 * tig + 8);
  }

  float O[16][4];
  #pragma unroll
  for (int u = 0; u < 16; u++)
    #pragma unroll
    for (int q = 0; q < 4; q++) O[u][q] = 0.f;
  float m0 = -1e30f, m1 = -1e30f, l0 = 0.f, l1 = 0.f;

  int ntiles = qt + 1;
  int pf_r = tid >> 4, pf_d = (tid & 15) * 8;

  auto prefetch = [&](int kt, int buf){
    uint32_t db = sbase + (uint32_t)buf * AT_STF * 2;
    const __half* kg = base + DMODEL + (size_t)(kt * 128 + pf_r) * (3 * DMODEL) + pf_d;
    #pragma unroll
    for (int it = 0; it < 8; it++){
      uint32_t dk = db + ((pf_r + it * 16) * 136 + pf_d) * 2;
      const __half* src = kg + (size_t)(it * 16) * (3 * DMODEL);
      cpa16(dk, src);                      // K
      cpa16(dk + AT_TF * 2, src + DMODEL); // V
    }
    cp_commit();
  };
  prefetch(0, 0);

  for (int kt = 0; kt < ntiles; kt++){
    int buf = kt & 1;
    if (kt + 1 < ntiles){ prefetch(kt + 1, buf ^ 1); cp_wait1(); }
    else cp_wait0();
    __syncthreads();

    int k0 = kt * 128;
    {
      const __half* Ks = smh + buf * AT_STF;

      // S = Q @ K^T : 16 n8 tiles over 128 keys
      float s[16][4];
      #pragma unroll
      for (int t = 0; t < 16; t++)
        #pragma unroll
        for (int q = 0; q < 4; q++) s[t][q] = 0.f;
      #pragma unroll
      for (int j = 0; j < 8; j++){
        #pragma unroll
        for (int t = 0; t < 16; t++){
          const __half* bb = Ks + (8 * t + gid) * 136 + 16 * j;
          uint32_t bf[2];
          bf[0] = *(const uint32_t*)(bb + 2 * tig);
          bf[1] = *(const uint32_t*)(bb + 2 * tig + 8);
          mma16(s[t], qa[j], bf);
        }
      }

      // scale + causal mask (only final tile is diagonal) + online softmax
      bool dg = (kt == qt);
      float mx0 = -1e30f, mx1 = -1e30f;
      #pragma unroll
      for (int t = 0; t < 16; t++){
        float c0 = s[t][0] * scl, c1 = s[t][1] * scl;
        float c2 = s[t][2] * scl, c3 = s[t][3] * scl;
        if (dg){
          int g0 = k0 + 8 * t + 2 * tig;
          if (g0     > r0)     c0 = -1e30f;
          if (g0 + 1 > r0)     c1 = -1e30f;
          if (g0     > r0 + 8) c2 = -1e30f;
          if (g0 + 1 > r0 + 8) c3 = -1e30f;
        }
        s[t][0] = c0; s[t][1] = c1; s[t][2] = c2; s[t][3] = c3;
        mx0 = fmaxf(mx0, fmaxf(c0, c1));
        mx1 = fmaxf(mx1, fmaxf(c2, c3));
      }
      #pragma unroll
      for (int m = 1; m < 4; m <<= 1){
        mx0 = fmaxf(mx0, __shfl_xor_sync(0xffffffffu, mx0, m));
        mx1 = fmaxf(mx1, __shfl_xor_sync(0xffffffffu, mx1, m));
      }
      float mn0 = fmaxf(m0, mx0), mn1 = fmaxf(m1, mx1);
      float cr0 = __expf(m0 - mn0), cr1 = __expf(m1 - mn1);
      m0 = mn0; m1 = mn1;
      float ls0 = 0.f, ls1 = 0.f;
      #pragma unroll
      for (int t = 0; t < 16; t++){
        s[t][0] = __expf(s[t][0] - mn0);
        s[t][1] = __expf(s[t][1] - mn0);
        s[t][2] = __expf(s[t][2] - mn1);
        s[t][3] = __expf(s[t][3] - mn1);
        ls0 += s[t][0] + s[t][1];
        ls1 += s[t][2] + s[t][3];
      }
      #pragma unroll
      for (int m = 1; m < 4; m <<= 1){
        ls0 += __shfl_xor_sync(0xffffffffu, ls0, m);
        ls1 += __shfl_xor_sync(0xffffffffu, ls1, m);
      }
      l0 = l0 * cr0 + ls0;
      l1 = l1 * cr1 + ls1;
      #pragma unroll
      for (int u = 0; u < 16; u++){
        O[u][0] *= cr0; O[u][1] *= cr0;
        O[u][2] *= cr1; O[u][3] *= cr1;
      }

      // O += P @ V  (P from S accumulators; V via ldmatrix.trans)
      #pragma unroll
      for (int j2 = 0; j2 < 8; j2++){
        uint32_t pa[4];
        pa[0] = packh2(s[2*j2][0],   s[2*j2][1]);
        pa[1] = packh2(s[2*j2][2],   s[2*j2][3]);
        pa[2] = packh2(s[2*j2+1][0], s[2*j2+1][1]);
        pa[3] = packh2(s[2*j2+1][2], s[2*j2+1][3]);
        uint32_t vrow = sbase + (uint32_t)buf * AT_STF * 2 + AT_TF * 2
                      + ((16 * j2 + (lane & 15)) * 136) * 2;
        #pragma unroll
        for (int u = 0; u < 16; u++){
          uint32_t b0, b1;
          ldmx2t(b0, b1, vrow + 16 * u);
          uint32_t bf[2] = {b0, b1};
          mma16(O[u], pa, bf);
        }
      }
    }
    __syncthreads();
  }

  float i0 = 1.0f / l0, i1 = 1.0f / l1;
  __half* o0 = av + ((size_t)(b * SEQ) + r0) * DMODEL + h * 128;
  __half* o1 = o0 + (size_t)8 * DMODEL;
  #pragma unroll
  for (int u = 0; u < 16; u++){
    *(__half2*)&o0[8 * u + 2 * tig] = __floats2half2_rn(O[u][0] * i0, O[u][1] * i0);
    *(__half2*)&o1[8 * u + 2 * tig] = __floats2half2_rn(O[u][2] * i1, O[u][3] * i1);
  }
}

// ---------------- launch ----------------
extern "C" void kernel_launch(void* const* d_in, const int* in_sizes, int n_in,
                              void* d_out, int out_size)
{
  const float* x     = (const float*)d_in[0];
  const float* ln1_g = (const float*)d_in[1];
  const float* ln1_b = (const float*)d_in[2];
  const float* qkv_w = (const float*)d_in[3];
  const float* qkv_b = (const float*)d_in[4];
  const float* out_w = (const float*)d_in[5];
  const float* out_b = (const float*)d_in[6];
  const float* ln2_g = (const float*)d_in[7];
  const float* ln2_b = (const float*)d_in[8];
  const float* w1    = (const float*)d_in[9];
  const float* b1    = (const float*)d_in[10];
  const float* w2    = (const float*)d_in[11];
  const float* b2    = (const float*)d_in[12];
  float* out = (float*)d_out;

  __half *h_p, *qkv_p, *av_p, *ffn_p, *wqkv_p, *wout_p, *w1_p, *w2_p;
  float *x1_p;
  cudaGetSymbolAddress((void**)&h_p,    g_h);
  cudaGetSymbolAddress((void**)&qkv_p,  g_qkv);
  cudaGetSymbolAddress((void**)&av_p,   g_av);
  cudaGetSymbolAddress((void**)&x1_p,   g_x1);
  cudaGetSymbolAddress((void**)&ffn_p,  g_ffn);
  cudaGetSymbolAddress((void**)&wqkv_p, g_wqkv);
  cudaGetSymbolAddress((void**)&wout_p, g_wout);
  cudaGetSymbolAddress((void**)&w1_p,   g_w1);
  cudaGetSymbolAddress((void**)&w2_p,   g_w2);

  cudaFuncSetAttribute(attn_h, cudaFuncAttributeMaxDynamicSharedMemorySize, AT_SMEM);
  cudaFuncSetAttribute(hgemm_w<0>, cudaFuncAttributeMaxDynamicSharedMemorySize, HW_SMEM);
  cudaFuncSetAttribute(hgemm_w<1>, cudaFuncAttributeMaxDynamicSharedMemorySize, HW_SMEM);

  // fused weight transpose (fp32[K][N] -> fp16[N][K], all 4 matrices)
  wtrans_all<<<WT_TILES, 256>>>(qkv_w, wqkv_p, out_w, wout_p, w1, w1_p, w2, w2_p);

  // 1. LN1 -> fp16
  ln_kernel<<<NTOK, 256>>>(x, ln1_g, ln1_b, h_p);

  // 2. QKV (fp16 out)
  hgemm_w<0><<<dim3(24, 32), 256, HW_SMEM>>>(h_p, wqkv_p, qkv_b, qkv_p,
                                             3 * DMODEL, DMODEL);

  // 3. fp16 flash attention (K-tile 128)
  attn_h<<<dim3(SEQ / 128, 2 * NHEAD), 256, AT_SMEM>>>(qkv_p, av_p);

  // 4. x1 = x + av @ out_w + out_b (fp32 out)
  hgemm_n<<<dim3(16, 32), 256>>>(av_p, wout_p, out_b, x, x1_p, DMODEL, DMODEL);

  // 5. LN2 -> fp16
  ln_kernel<<<NTOK, 256>>>(x1_p, ln2_g, ln2_b, h_p);

  // 6. ffn = gelu(h @ w1 + b1) (fp16 out)
  hgemm_w<1><<<dim3(32, 32), 256, HW_SMEM>>>(h_p, w1_p, b1, ffn_p, FFDIM, DMODEL);

  // 7. out = x1 + ffn @ w2 + b2 (fp32 out)
  hgemm_n<<<dim3(16, 32), 256>>>(ffn_p, w2_p, b2, x1_p, out, DMODEL, FFDIM);
}

// round 10
// speedup vs baseline: 1.8872x; 1.0608x over previous
#include <cuda_runtime.h>
#include <cuda_fp16.h>
#include <math.h>
#include <stdint.h>

#define SEQ     2048
#define DMODEL  2048
#define NHEAD   16
#define FFDIM   8192
#define NTOK    4096
#define LN_EPS  1e-5f

// ---------------- scratch ----------------
__device__ __half g_h   [(size_t)NTOK * DMODEL];
__device__ __half g_qkv [(size_t)NTOK * 3 * DMODEL];
__device__ __half g_av  [(size_t)NTOK * DMODEL];
__device__ float  g_x1  [(size_t)NTOK * DMODEL];
__device__ __half g_ffn [(size_t)NTOK * FFDIM];
__device__ __half g_wqkv[(size_t)3 * DMODEL * DMODEL];  // [N][K]
__device__ __half g_wout[(size_t)DMODEL * DMODEL];
__device__ __half g_w1  [(size_t)FFDIM * DMODEL];
__device__ __half g_w2  [(size_t)DMODEL * FFDIM];

// ---------------- helpers ----------------
__device__ __forceinline__ uint32_t s2u(const void* p){
  uint32_t a;
  asm("{ .reg .u64 t; cvta.to.shared.u64 t, %1; cvt.u32.u64 %0, t; }" : "=r"(a) : "l"(p));
  return a;
}
__device__ __forceinline__ void cpa16(uint32_t dst, const void* src){
  asm volatile("cp.async.cg.shared.global [%0], [%1], 16;" :: "r"(dst), "l"(src));
}
__device__ __forceinline__ void cp_commit(){ asm volatile("cp.async.commit_group;"); }
__device__ __forceinline__ void cp_wait0(){ asm volatile("cp.async.wait_group 0;" ::: "memory"); }
__device__ __forceinline__ void cp_wait1(){ asm volatile("cp.async.wait_group 1;" ::: "memory"); }
__device__ __forceinline__ void mma16(float* c, const uint32_t* a, const uint32_t* b){
  asm volatile("mma.sync.aligned.m16n8k16.row.col.f32.f16.f16.f32 "
    "{%0,%1,%2,%3}, {%4,%5,%6,%7}, {%8,%9}, {%0,%1,%2,%3};"
    : "+f"(c[0]), "+f"(c[1]), "+f"(c[2]), "+f"(c[3])
    : "r"(a[0]), "r"(a[1]), "r"(a[2]), "r"(a[3]), "r"(b[0]), "r"(b[1]));
}
__device__ __forceinline__ void ldmx4(uint32_t* r, uint32_t addr){
  asm volatile("ldmatrix.sync.aligned.m8n8.x4.shared.b16 {%0,%1,%2,%3}, [%4];"
    : "=r"(r[0]), "=r"(r[1]), "=r"(r[2]), "=r"(r[3]) : "r"(addr));
}
__device__ __forceinline__ void ldmx2t(uint32_t& r0, uint32_t& r1, uint32_t addr){
  asm volatile("ldmatrix.sync.aligned.m8n8.x2.trans.shared.b16 {%0,%1}, [%2];"
    : "=r"(r0), "=r"(r1) : "r"(addr));
}
__device__ __forceinline__ uint32_t packh2(float lo, float hi){
  __half2 h = __floats2half2_rn(lo, hi);
  return *(uint32_t*)&h;
}
__device__ __forceinline__ float gelu_exact(float t){
  return 0.5f * t * (1.0f + erff(t * 0.70710678118654752f));
}

// ---- fused weight transpose: all 4 matrices, W[K][N] fp32 -> Wt[N][K] fp16 ----
#define WT_TILES 49152
__global__ __launch_bounds__(256) void wtrans_all(
    const float* __restrict__ qkv_w, __half* __restrict__ o_qkv,
    const float* __restrict__ out_w, __half* __restrict__ o_out,
    const float* __restrict__ w1,    __half* __restrict__ o_w1,
    const float* __restrict__ w2,    __half* __restrict__ o_w2)
{
  __shared__ float s[32][33];
  int bid = blockIdx.x;
  const float* W; __half* Wt; int K, N, nx, tile;
  if (bid < 12288){ W = qkv_w; Wt = o_qkv; K = 2048; N = 6144; nx = 192; tile = bid; }
  else if (bid < 16384){ W = out_w; Wt = o_out; K = 2048; N = 2048; nx = 64; tile = bid - 12288; }
  else if (bid < 32768){ W = w1; Wt = o_w1; K = 2048; N = 8192; nx = 256; tile = bid - 16384; }
  else { W = w2; Wt = o_w2; K = 8192; N = 2048; nx = 64; tile = bid - 32768; }
  int n0 = (tile % nx) * 32, k0 = (tile / nx) * 32;
  int tid = threadIdx.x;
  #pragma unroll
  for (int i = 0; i < 4; i++){
    int idx = tid + i * 256;
    int r = idx >> 5, c = idx & 31;
    s[r][c] = W[(size_t)(k0 + r) * N + n0 + c];
  }
  __syncthreads();
  #pragma unroll
  for (int i = 0; i < 2; i++){
    int c = tid + i * 256;
    int n = c >> 4, k2 = (c & 15) * 2;
    __half2 h = __floats2half2_rn(s[k2][n], s[k2 + 1][n]);
    *(__half2*)&Wt[(size_t)(n0 + n) * K + k0 + k2] = h;
  }
}

// ---- LayerNorm fp32 in -> fp16 out ----
__global__ __launch_bounds__(256) void ln_kernel(
    const float* __restrict__ x, const float* __restrict__ gamma,
    const float* __restrict__ beta, __half* __restrict__ out)
{
  int row = blockIdx.x;
  int tid = threadIdx.x;
  const float4* xr = (const float4*)(x + (size_t)row * DMODEL);
  float4 v0 = xr[tid];
  float4 v1 = xr[tid + 256];
  float s  = v0.x + v0.y + v0.z + v0.w + v1.x + v1.y + v1.z + v1.w;
  float sq = v0.x*v0.x + v0.y*v0.y + v0.z*v0.z + v0.w*v0.w
           + v1.x*v1.x + v1.y*v1.y + v1.z*v1.z + v1.w*v1.w;
  #pragma unroll
  for (int m = 16; m > 0; m >>= 1){
    s  += __shfl_xor_sync(0xffffffffu, s,  m);
    sq += __shfl_xor_sync(0xffffffffu, sq, m);
  }
  __shared__ float red_s[8], red_q[8], bc[2];
  int warp = tid >> 5, lane = tid & 31;
  if (lane == 0){ red_s[warp] = s; red_q[warp] = sq; }
  __syncthreads();
  if (tid == 0){
    float ts = 0.f, tq = 0.f;
    #pragma unroll
    for (int i = 0; i < 8; i++){ ts += red_s[i]; tq += red_q[i]; }
    float mu  = ts * (1.0f / DMODEL);
    float var = tq * (1.0f / DMODEL) - mu * mu;
    bc[0] = mu; bc[1] = rsqrtf(var + LN_EPS);
  }
  __syncthreads();
  float mu = bc[0], rinv = bc[1];
  const float4* gv = (const float4*)gamma;
  const float4* bv = (const float4*)beta;
  float4 g0 = gv[tid], b0 = bv[tid];
  float4 g1 = gv[tid + 256], b1 = bv[tid + 256];
  __half2* ov = (__half2*)(out + (size_t)row * DMODEL);
  ov[2*tid]           = __floats2half2_rn((v0.x-mu)*rinv*g0.x+b0.x, (v0.y-mu)*rinv*g0.y+b0.y);
  ov[2*tid + 1]       = __floats2half2_rn((v0.z-mu)*rinv*g0.z+b0.z, (v0.w-mu)*rinv*g0.w+b0.w);
  ov[512 + 2*tid]     = __floats2half2_rn((v1.x-mu)*rinv*g1.x+b1.x, (v1.y-mu)*rinv*g1.y+b1.y);
  ov[512 + 2*tid + 1] = __floats2half2_rn((v1.z-mu)*rinv*g1.z+b1.z, (v1.w-mu)*rinv*g1.w+b1.w);
}

// ---------------------------------------------------------------------------
// fp16 GEMM wide: tile 128x256, BK=32, occ1, 3-stage, ldmatrix fragment loads.
// ---------------------------------------------------------------------------
#define HW_AF   (128 * 40)
#define HW_BF   (256 * 40)
#define HW_STF  (HW_AF + HW_BF)
#define HW_SMEM (3 * HW_STF * 2)

template<int EPI>
__global__ __launch_bounds__(256, 1) void hgemm_w(
    const __half* __restrict__ A, const __half* __restrict__ Bt,
    const float* __restrict__ bias, __half* __restrict__ C, int N, int K)
{
  extern __shared__ __half smh[];
  int tid = threadIdx.x, lane = tid & 31, warp = tid >> 5;
  int bx = blockIdx.x, by = blockIdx.y;
  int wm = (warp >> 2) * 64, wn = (warp & 3) * 64;
  int gid = lane >> 2, tig = lane & 3;

  int a_r = tid >> 2, ko = (tid & 3) * 8;
  const __half* Ag = A + (size_t)(by * 128 + a_r) * K + ko;
  const __half* Bg = Bt + (size_t)(bx * 256 + a_r) * K + ko;

  uint32_t smb = s2u(smh);
  uint32_t asd = smb + (a_r * 40 + ko) * 2;
  uint32_t bsd = smb + (HW_AF + a_r * 40 + ko) * 2;

  // ldmatrix per-lane base addresses (stage/k offsets added in loop)
  uint32_t a_lm[4], b_lm[4];
  #pragma unroll
  for (int mi = 0; mi < 4; mi++)
    a_lm[mi] = smb + (((wm + mi * 16 + (lane & 15)) * 40) + ((lane >> 4) * 8)) * 2;
  #pragma unroll
  for (int tp = 0; tp < 4; tp++)
    b_lm[tp] = smb + (HW_AF
             + (wn + 16 * tp + ((lane & 16) ? 8 : 0) + (lane & 7)) * 40
             + ((lane & 8) ? 8 : 0)) * 2;

  float c[4][8][4];
  #pragma unroll
  for (int mi = 0; mi < 4; mi++)
    #pragma unroll
    for (int ni = 0; ni < 8; ni++)
      #pragma unroll
      for (int q = 0; q < 4; q++) c[mi][ni][q] = 0.f;

  int nk = K >> 5;
  auto issue = [&](int kb, int st){
    uint32_t off = (uint32_t)st * HW_STF * 2;
    cpa16(asd + off,            Ag + (size_t)kb * 32);
    cpa16(asd + off + 64*40*2,  Ag + (size_t)kb * 32 + (size_t)64 * K);
    #pragma unroll
    for (int i = 0; i < 4; i++)
      cpa16(bsd + off + i * 64*40*2, Bg + (size_t)kb * 32 + (size_t)(64 * i) * K);
    cp_commit();
  };
  issue(0, 0);
  if (nk > 1) issue(1, 1);

  for (int kb = 0; kb < nk; kb++){
    int st = kb % 3;
    if (kb + 1 < nk) cp_wait1(); else cp_wait0();
    __syncthreads();
    uint32_t soff = (uint32_t)st * HW_STF * 2;
    #pragma unroll
    for (int ks = 0; ks < 2; ks++){
      uint32_t koff = soff + ks * 32;
      uint32_t a[4][4], b[8][2];
      #pragma unroll
      for (int mi = 0; mi < 4; mi++)
        ldmx4(a[mi], a_lm[mi] + koff);
      #pragma unroll
      for (int tp = 0; tp < 4; tp++){
        uint32_t r[4];
        ldmx4(r, b_lm[tp] + koff);
        b[2*tp][0] = r[0]; b[2*tp][1] = r[1];
        b[2*tp+1][0] = r[2]; b[2*tp+1][1] = r[3];
      }
      #pragma unroll
      for (int mi = 0; mi < 4; mi++)
        #pragma unroll
        for (int t = 0; t < 8; t++)
          mma16(c[mi][t], a[mi], b[t]);
    }
    __syncthreads();
    if (kb + 2 < nk) issue(kb + 2, (kb + 2) % 3);
  }

  #pragma unroll
  for (int ni = 0; ni < 8; ni++){
    int col = bx * 256 + wn + ni * 8 + 2 * tig;
    float bb0 = bias[col], bb1 = bias[col + 1];
    #pragma unroll
    for (int mi = 0; mi < 4; mi++){
      int row0 = by * 128 + wm + mi * 16 + gid;
      float v00 = c[mi][ni][0] + bb0, v01 = c[mi][ni][1] + bb1;
      float v10 = c[mi][ni][2] + bb0, v11 = c[mi][ni][3] + bb1;
      if (EPI == 1){
        v00 = gelu_exact(v00); v01 = gelu_exact(v01);
        v10 = gelu_exact(v10); v11 = gelu_exact(v11);
      }
      *(__half2*)&C[(size_t)row0 * N + col]       = __floats2half2_rn(v00, v01);
      *(__half2*)&C[(size_t)(row0 + 8) * N + col] = __floats2half2_rn(v10, v11);
    }
  }
}

// ---------------------------------------------------------------------------
// fp16 GEMM narrow: tile 128x128, occ2, 2-stage, ldmatrix loads. -> fp32 +res.
// ---------------------------------------------------------------------------
__global__ __launch_bounds__(256, 2) void hgemm_n(
    const __half* __restrict__ A, const __half* __restrict__ Bt,
    const float* __restrict__ bias, const float* __restrict__ res,
    float* __restrict__ C, int N, int K)
{
  __shared__ __half As[2][128 * 40];
  __shared__ __half Bs[2][128 * 40];

  int tid = threadIdx.x, lane = tid & 31, warp = tid >> 5;
  int bx = blockIdx.x, by = blockIdx.y;
  int wm = (warp >> 2) * 64, wn = (warp & 3) * 32;
  int gid = lane >> 2, tig = lane & 3;

  int a_r = tid >> 2, ko = (tid & 3) * 8;
  const __half* Ag = A + (size_t)(by * 128 + a_r) * K + ko;
  const __half* Bg = Bt + (size_t)(bx * 128 + a_r) * K + ko;
  uint32_t asd = s2u(&As[0][a_r * 40 + ko]);
  uint32_t bsd = s2u(&Bs[0][a_r * 40 + ko]);
  const uint32_t stB = 128 * 40 * 2;

  uint32_t a_lm[4], b_lm[2];
  #pragma unroll
  for (int mi = 0; mi < 4; mi++)
    a_lm[mi] = s2u(&As[0][0]) + (((wm + mi * 16 + (lane & 15)) * 40) + ((lane >> 4) * 8)) * 2;
  #pragma unroll
  for (int tp = 0; tp < 2; tp++)
    b_lm[tp] = s2u(&Bs[0][0])
             + ((wn + 16 * tp + ((lane & 16) ? 8 : 0) + (lane & 7)) * 40
             + ((lane & 8) ? 8 : 0)) * 2;

  float c[4][4][4];
  #pragma unroll
  for (int mi = 0; mi < 4; mi++)
    #pragma unroll
    for (int ni = 0; ni < 4; ni++)
      #pragma unroll
      for (int q = 0; q < 4; q++) c[mi][ni][q] = 0.f;

  int nk = K >> 5;
  auto issue = [&](int kb, int st){
    uint32_t off = st ? stB : 0;
    cpa16(asd + off,           Ag + (size_t)kb * 32);
    cpa16(asd + off + 64*40*2, Ag + (size_t)kb * 32 + (size_t)64 * K);
    cpa16(bsd + off,           Bg + (size_t)kb * 32);
    cpa16(bsd + off + 64*40*2, Bg + (size_t)kb * 32 + (size_t)64 * K);
    cp_commit();
  };
  issue(0, 0);

  for (int kb = 0; kb < nk; kb++){
    int st = kb & 1;
    cp_wait0();
    __syncthreads();
    if (kb + 1 < nk) issue(kb + 1, st ^ 1);
    uint32_t soff = st ? stB : 0;
    #pragma unroll
    for (int ks = 0; ks < 2; ks++){
      uint32_t koff = soff + ks * 32;
      uint32_t a[4][4], b[4][2];
      #pragma unroll
      for (int mi = 0; mi < 4; mi++)
        ldmx4(a[mi], a_lm[mi] + koff);
      #pragma unroll
      for (int tp = 0; tp < 2; tp++){
        uint32_t r[4];
        ldmx4(r, b_lm[tp] + koff);
        b[2*tp][0] = r[0]; b[2*tp][1] = r[1];
        b[2*tp+1][0] = r[2]; b[2*tp+1][1] = r[3];
      }
      #pragma unroll
      for (int mi = 0; mi < 4; mi++)
        #pragma unroll
        for (int t = 0; t < 4; t++)
          mma16(c[mi][t], a[mi], b[t]);
    }
    __syncthreads();
  }

  #pragma unroll
  for (int ni = 0; ni < 4; ni++){
    int col = bx * 128 + wn + ni * 8 + 2 * tig;
    float bb0 = bias[col], bb1 = bias[col + 1];
    #pragma unroll
    for (int mi = 0; mi < 4; mi++){
      int row0 = by * 128 + wm + mi * 16 + gid;
      float2 r0 = *(const float2*)&res[(size_t)row0 * N + col];
      float2 r1 = *(const float2*)&res[(size_t)(row0 + 8) * N + col];
      float2 v0 = make_float2(c[mi][ni][0] + bb0 + r0.x, c[mi][ni][1] + bb1 + r0.y);
      float2 v1 = make_float2(c[mi][ni][2] + bb0 + r1.x, c[mi][ni][3] + bb1 + r1.y);
      *(float2*)&C[(size_t)row0 * N + col]       = v0;
      *(float2*)&C[(size_t)(row0 + 8) * N + col] = v1;
    }
  }
}

// ---------------------------------------------------------------------------
// fp16 mma flash attention (R9 design, K-tile 128).
// ---------------------------------------------------------------------------
#define AT_TF   (128 * 136)
#define AT_STF  (2 * AT_TF)
#define AT_SMEM (2 * AT_STF * 2)

__global__ __launch_bounds__(256, 1) void attn_h(
    const __half* __restrict__ qkv, __half* __restrict__ av)
{
  extern __shared__ __half smh[];
  uint32_t sbase = s2u(smh);

  int qt = blockIdx.x, bh = blockIdx.y;
  int b = bh >> 4, h = bh & 15;
  int q0 = qt * 128;
  int tid = threadIdx.x, warp = tid >> 5, lane = tid & 31;
  int gid = lane >> 2, tig = lane & 3;
  int wq = warp * 16;
  const float scl = 0.08838834764831845f;

  const __half* base = qkv + (size_t)(b * SEQ) * (3 * DMODEL) + h * 128;

  int r0 = q0 + wq + gid;
  const __half* Qp0 = base + (size_t)r0 * (3 * DMODEL);
  const __half* Qp1 = Qp0 + (size_t)8 * (3 * DMODEL);
  uint32_t qa[8][4];
  #pragma unroll
  for (int j = 0; j < 8; j++){
    qa[j][0] = *(const uint32_t*)(Qp0 + 16 * j + 2 * tig);
    qa[j][1] = *(const uint32_t*)(Qp1 + 16 * j + 2 * tig);
    qa[j][2] = *(const uint32_t*)(Qp0 + 16 * j + 2 * tig + 8);
    qa[j][3] = *(const uint32_t*)(Qp1 + 16 * j + 2 * tig + 8);
  }

  float O[16][4];
  #pragma unroll
  for (int u = 0; u < 16; u++)
    #pragma unroll
    for (int q = 0; q < 4; q++) O[u][q] = 0.f;
  float m0 = -1e30f, m1 = -1e30f, l0 = 0.f, l1 = 0.f;

  int ntiles = qt + 1;
  int pf_r = tid >> 4, pf_d = (tid & 15) * 8;

  auto prefetch = [&](int kt, int buf){
    uint32_t db = sbase + (uint32_t)buf * AT_STF * 2;
    const __half* kg = base + DMODEL + (size_t)(kt * 128 + pf_r) * (3 * DMODEL) + pf_d;
    #pragma unroll
    for (int it = 0; it < 8; it++){
      uint32_t dk = db + ((pf_r + it * 16) * 136 + pf_d) * 2;
      const __half* src = kg + (size_t)(it * 16) * (3 * DMODEL);
      cpa16(dk, src);
      cpa16(dk + AT_TF * 2, src + DMODEL);
    }
    cp_commit();
  };
  prefetch(0, 0);

  // K-frag ldmatrix lane base (x2: lanes 0-7 rows n, 8-15 rows n koff+8)
  for (int kt = 0; kt < ntiles; kt++){
    int buf = kt & 1;
    if (kt + 1 < ntiles){ prefetch(kt + 1, buf ^ 1); cp_wait1(); }
    else cp_wait0();
    __syncthreads();

    int k0 = kt * 128;
    {
      const __half* Ks = smh + buf * AT_STF;

      float s[16][4];
      #pragma unroll
      for (int t = 0; t < 16; t++)
        #pragma unroll
        for (int q = 0; q < 4; q++) s[t][q] = 0.f;
      #pragma unroll
      for (int j = 0; j < 8; j++){
        #pragma unroll
        for (int t = 0; t < 16; t++){
          const __half* bb = Ks + (8 * t + gid) * 136 + 16 * j;
          uint32_t bf[2];
          bf[0] = *(const uint32_t*)(bb + 2 * tig);
          bf[1] = *(const uint32_t*)(bb + 2 * tig + 8);
          mma16(s[t], qa[j], bf);
        }
      }

      bool dg = (kt == qt);
      float mx0 = -1e30f, mx1 = -1e30f;
      #pragma unroll
      for (int t = 0; t < 16; t++){
        float c0 = s[t][0] * scl, c1 = s[t][1] * scl;
        float c2 = s[t][2] * scl, c3 = s[t][3] * scl;
        if (dg){
          int g0 = k0 + 8 * t + 2 * tig;
          if (g0     > r0)     c0 = -1e30f;
          if (g0 + 1 > r0)     c1 = -1e30f;
          if (g0     > r0 + 8) c2 = -1e30f;
          if (g0 + 1 > r0 + 8) c3 = -1e30f;
        }
        s[t][0] = c0; s[t][1] = c1; s[t][2] = c2; s[t][3] = c3;
        mx0 = fmaxf(mx0, fmaxf(c0, c1));
        mx1 = fmaxf(mx1, fmaxf(c2, c3));
      }
      #pragma unroll
      for (int m = 1; m < 4; m <<= 1){
        mx0 = fmaxf(mx0, __shfl_xor_sync(0xffffffffu, mx0, m));
        mx1 = fmaxf(mx1, __shfl_xor_sync(0xffffffffu, mx1, m));
      }
      float mn0 = fmaxf(m0, mx0), mn1 = fmaxf(m1, mx1);
      float cr0 = __expf(m0 - mn0), cr1 = __expf(m1 - mn1);
      m0 = mn0; m1 = mn1;
      float ls0 = 0.f, ls1 = 0.f;
      #pragma unroll
      for (int t = 0; t < 16; t++){
        s[t][0] = __expf(s[t][0] - mn0);
        s[t][1] = __expf(s[t][1] - mn0);
        s[t][2] = __expf(s[t][2] - mn1);
        s[t][3] = __expf(s[t][3] - mn1);
        ls0 += s[t][0] + s[t][1];
        ls1 += s[t][2] + s[t][3];
      }
      #pragma unroll
      for (int m = 1; m < 4; m <<= 1){
        ls0 += __shfl_xor_sync(0xffffffffu, ls0, m);
        ls1 += __shfl_xor_sync(0xffffffffu, ls1, m);
      }
      l0 = l0 * cr0 + ls0;
      l1 = l1 * cr1 + ls1;
      #pragma unroll
      for (int u = 0; u < 16; u++){
        O[u][0] *= cr0; O[u][1] *= cr0;
        O[u][2] *= cr1; O[u][3] *= cr1;
      }

      #pragma unroll
      for (int j2 = 0; j2 < 8; j2++){
        uint32_t pa[4];
        pa[0] = packh2(s[2*j2][0],   s[2*j2][1]);
        pa[1] = packh2(s[2*j2][2],   s[2*j2][3]);
        pa[2] = packh2(s[2*j2+1][0], s[2*j2+1][1]);
        pa[3] = packh2(s[2*j2+1][2], s[2*j2+1][3]);
        uint32_t vrow = sbase + (uint32_t)buf * AT_STF * 2 + AT_TF * 2
                      + ((16 * j2 + (lane & 15)) * 136) * 2;
        #pragma unroll
        for (int u = 0; u < 16; u++){
          uint32_t b0, b1;
          ldmx2t(b0, b1, vrow + 16 * u);
          uint32_t bf[2] = {b0, b1};
          mma16(O[u], pa, bf);
        }
      }
    }
    __syncthreads();
  }

  float i0 = 1.0f / l0, i1 = 1.0f / l1;
  __half* o0 = av + ((size_t)(b * SEQ) + r0) * DMODEL + h * 128;
  __half* o1 = o0 + (size_t)8 * DMODEL;
  #pragma unroll
  for (int u = 0; u < 16; u++){
    *(__half2*)&o0[8 * u + 2 * tig] = __floats2half2_rn(O[u][0] * i0, O[u][1] * i0);
    *(__half2*)&o1[8 * u + 2 * tig] = __floats2half2_rn(O[u][2] * i1, O[u][3] * i1);
  }
}

// ---------------- launch ----------------
extern "C" void kernel_launch(void* const* d_in, const int* in_sizes, int n_in,
                              void* d_out, int out_size)
{
  const float* x     = (const float*)d_in[0];
  const float* ln1_g = (const float*)d_in[1];
  const float* ln1_b = (const float*)d_in[2];
  const float* qkv_w = (const float*)d_in[3];
  const float* qkv_b = (const float*)d_in[4];
  const float* out_w = (const float*)d_in[5];
  const float* out_b = (const float*)d_in[6];
  const float* ln2_g = (const float*)d_in[7];
  const float* ln2_b = (const float*)d_in[8];
  const float* w1    = (const float*)d_in[9];
  const float* b1    = (const float*)d_in[10];
  const float* w2    = (const float*)d_in[11];
  const float* b2    = (const float*)d_in[12];
  float* out = (float*)d_out;

  __half *h_p, *qkv_p, *av_p, *ffn_p, *wqkv_p, *wout_p, *w1_p, *w2_p;
  float *x1_p;
  cudaGetSymbolAddress((void**)&h_p,    g_h);
  cudaGetSymbolAddress((void**)&qkv_p,  g_qkv);
  cudaGetSymbolAddress((void**)&av_p,   g_av);
  cudaGetSymbolAddress((void**)&x1_p,   g_x1);
  cudaGetSymbolAddress((void**)&ffn_p,  g_ffn);
  cudaGetSymbolAddress((void**)&wqkv_p, g_wqkv);
  cudaGetSymbolAddress((void**)&wout_p, g_wout);
  cudaGetSymbolAddress((void**)&w1_p,   g_w1);
  cudaGetSymbolAddress((void**)&w2_p,   g_w2);

  cudaFuncSetAttribute(attn_h, cudaFuncAttributeMaxDynamicSharedMemorySize, AT_SMEM);
  cudaFuncSetAttribute(hgemm_w<0>, cudaFuncAttributeMaxDynamicSharedMemorySize, HW_SMEM);
  cudaFuncSetAttribute(hgemm_w<1>, cudaFuncAttributeMaxDynamicSharedMemorySize, HW_SMEM);

  wtrans_all<<<WT_TILES, 256>>>(qkv_w, wqkv_p, out_w, wout_p, w1, w1_p, w2, w2_p);

  ln_kernel<<<NTOK, 256>>>(x, ln1_g, ln1_b, h_p);

  hgemm_w<0><<<dim3(24, 32), 256, HW_SMEM>>>(h_p, wqkv_p, qkv_b, qkv_p,
                                             3 * DMODEL, DMODEL);

  attn_h<<<dim3(SEQ / 128, 2 * NHEAD), 256, AT_SMEM>>>(qkv_p, av_p);

  hgemm_n<<<dim3(16, 32), 256>>>(av_p, wout_p, out_b, x, x1_p, DMODEL, DMODEL);

  ln_kernel<<<NTOK, 256>>>(x1_p, ln2_g, ln2_b, h_p);

  hgemm_w<1><<<dim3(32, 32), 256, HW_SMEM>>>(h_p, w1_p, b1, ffn_p, FFDIM, DMODEL);

  hgemm_n<<<dim3(16, 32), 256>>>(ffn_p, w2_p, b2, x1_p, out, DMODEL, FFDIM);
}

// round 11
// speedup vs baseline: 2.1442x; 1.1362x over previous
#include <cuda_runtime.h>
#include <cuda_fp16.h>
#include <math.h>
#include <stdint.h>

#define SEQ     2048
#define DMODEL  2048
#define NHEAD   16
#define FFDIM   8192
#define NTOK    4096
#define LN_EPS  1e-5f

// ---------------- scratch ----------------
__device__ __half g_h   [(size_t)NTOK * DMODEL];
__device__ __half g_qkv [(size_t)NTOK * 3 * DMODEL];
__device__ __half g_av  [(size_t)NTOK * DMODEL];
__device__ float  g_x1  [(size_t)NTOK * DMODEL];
__device__ __half g_ffn [(size_t)NTOK * FFDIM];
__device__ __half g_wqkv[(size_t)3 * DMODEL * DMODEL];  // [N][K]
__device__ __half g_wout[(size_t)DMODEL * DMODEL];
__device__ __half g_w1  [(size_t)FFDIM * DMODEL];
__device__ __half g_w2  [(size_t)DMODEL * FFDIM];

// ---------------- helpers ----------------
__device__ __forceinline__ uint32_t s2u(const void* p){
  uint32_t a;
  asm("{ .reg .u64 t; cvta.to.shared.u64 t, %1; cvt.u32.u64 %0, t; }" : "=r"(a) : "l"(p));
  return a;
}
__device__ __forceinline__ void cpa16(uint32_t dst, const void* src){
  asm volatile("cp.async.cg.shared.global [%0], [%1], 16;" :: "r"(dst), "l"(src));
}
__device__ __forceinline__ void cp_commit(){ asm volatile("cp.async.commit_group;"); }
__device__ __forceinline__ void cp_wait0(){ asm volatile("cp.async.wait_group 0;" ::: "memory"); }
__device__ __forceinline__ void cp_wait1(){ asm volatile("cp.async.wait_group 1;" ::: "memory"); }
__device__ __forceinline__ void mma16(float* c, const uint32_t* a, const uint32_t* b){
  asm volatile("mma.sync.aligned.m16n8k16.row.col.f32.f16.f16.f32 "
    "{%0,%1,%2,%3}, {%4,%5,%6,%7}, {%8,%9}, {%0,%1,%2,%3};"
    : "+f"(c[0]), "+f"(c[1]), "+f"(c[2]), "+f"(c[3])
    : "r"(a[0]), "r"(a[1]), "r"(a[2]), "r"(a[3]), "r"(b[0]), "r"(b[1]));
}
__device__ __forceinline__ void ldmx4(uint32_t* r, uint32_t addr){
  asm volatile("ldmatrix.sync.aligned.m8n8.x4.shared.b16 {%0,%1,%2,%3}, [%4];"
    : "=r"(r[0]), "=r"(r[1]), "=r"(r[2]), "=r"(r[3]) : "r"(addr));
}
__device__ __forceinline__ void ldmx2t(uint32_t& r0, uint32_t& r1, uint32_t addr){
  asm volatile("ldmatrix.sync.aligned.m8n8.x2.trans.shared.b16 {%0,%1}, [%2];"
    : "=r"(r0), "=r"(r1) : "r"(addr));
}
__device__ __forceinline__ uint32_t packh2(float lo, float hi){
  __half2 h = __floats2half2_rn(lo, hi);
  return *(uint32_t*)&h;
}
__device__ __forceinline__ float gelu_exact(float t){
  return 0.5f * t * (1.0f + erff(t * 0.70710678118654752f));
}

// ---- fused weight transpose: all 4 matrices, W[K][N] fp32 -> Wt[N][K] fp16 ----
#define WT_TILES 49152
__global__ __launch_bounds__(256) void wtrans_all(
    const float* __restrict__ qkv_w, __half* __restrict__ o_qkv,
    const float* __restrict__ out_w, __half* __restrict__ o_out,
    const float* __restrict__ w1,    __half* __restrict__ o_w1,
    const float* __restrict__ w2,    __half* __restrict__ o_w2)
{
  __shared__ float s[32][33];
  int bid = blockIdx.x;
  const float* W; __half* Wt; int K, N, nx, tile;
  if (bid < 12288){ W = qkv_w; Wt = o_qkv; K = 2048; N = 6144; nx = 192; tile = bid; }
  else if (bid < 16384){ W = out_w; Wt = o_out; K = 2048; N = 2048; nx = 64; tile = bid - 12288; }
  else if (bid < 32768){ W = w1; Wt = o_w1; K = 2048; N = 8192; nx = 256; tile = bid - 16384; }
  else { W = w2; Wt = o_w2; K = 8192; N = 2048; nx = 64; tile = bid - 32768; }
  int n0 = (tile % nx) * 32, k0 = (tile / nx) * 32;
  int tid = threadIdx.x;
  #pragma unroll
  for (int i = 0; i < 4; i++){
    int idx = tid + i * 256;
    int r = idx >> 5, c = idx & 31;
    s[r][c] = W[(size_t)(k0 + r) * N + n0 + c];
  }
  __syncthreads();
  #pragma unroll
  for (int i = 0; i < 2; i++){
    int c = tid + i * 256;
    int n = c >> 4, k2 = (c & 15) * 2;
    __half2 h = __floats2half2_rn(s[k2][n], s[k2 + 1][n]);
    *(__half2*)&Wt[(size_t)(n0 + n) * K + k0 + k2] = h;
  }
}

// ---- LayerNorm fp32 in -> fp16 out ----
__global__ __launch_bounds__(256) void ln_kernel(
    const float* __restrict__ x, const float* __restrict__ gamma,
    const float* __restrict__ beta, __half* __restrict__ out)
{
  int row = blockIdx.x;
  int tid = threadIdx.x;
  const float4* xr = (const float4*)(x + (size_t)row * DMODEL);
  float4 v0 = xr[tid];
  float4 v1 = xr[tid + 256];
  float s  = v0.x + v0.y + v0.z + v0.w + v1.x + v1.y + v1.z + v1.w;
  float sq = v0.x*v0.x + v0.y*v0.y + v0.z*v0.z + v0.w*v0.w
           + v1.x*v1.x + v1.y*v1.y + v1.z*v1.z + v1.w*v1.w;
  #pragma unroll
  for (int m = 16; m > 0; m >>= 1){
    s  += __shfl_xor_sync(0xffffffffu, s,  m);
    sq += __shfl_xor_sync(0xffffffffu, sq, m);
  }
  __shared__ float red_s[8], red_q[8], bc[2];
  int warp = tid >> 5, lane = tid & 31;
  if (lane == 0){ red_s[warp] = s; red_q[warp] = sq; }
  __syncthreads();
  if (tid == 0){
    float ts = 0.f, tq = 0.f;
    #pragma unroll
    for (int i = 0; i < 8; i++){ ts += red_s[i]; tq += red_q[i]; }
    float mu  = ts * (1.0f / DMODEL);
    float var = tq * (1.0f / DMODEL) - mu * mu;
    bc[0] = mu; bc[1] = rsqrtf(var + LN_EPS);
  }
  __syncthreads();
  float mu = bc[0], rinv = bc[1];
  const float4* gv = (const float4*)gamma;
  const float4* bv = (const float4*)beta;
  float4 g0 = gv[tid], b0 = bv[tid];
  float4 g1 = gv[tid + 256], b1 = bv[tid + 256];
  __half2* ov = (__half2*)(out + (size_t)row * DMODEL);
  ov[2*tid]           = __floats2half2_rn((v0.x-mu)*rinv*g0.x+b0.x, (v0.y-mu)*rinv*g0.y+b0.y);
  ov[2*tid + 1]       = __floats2half2_rn((v0.z-mu)*rinv*g0.z+b0.z, (v0.w-mu)*rinv*g0.w+b0.w);
  ov[512 + 2*tid]     = __floats2half2_rn((v1.x-mu)*rinv*g1.x+b1.x, (v1.y-mu)*rinv*g1.y+b1.y);
  ov[512 + 2*tid + 1] = __floats2half2_rn((v1.z-mu)*rinv*g1.z+b1.z, (v1.w-mu)*rinv*g1.w+b1.w);
}

// ---------------------------------------------------------------------------
// fp16 GEMM wide: tile 128x256, BK=64, 2-stage, ldmatrix. occ1.
// ---------------------------------------------------------------------------
#define HW_AF   (128 * 72)           // halves
#define HW_BF   (256 * 72)
#define HW_STF  (HW_AF + HW_BF)      // 27648 halves per stage
#define HW_STB  (HW_STF * 2)         // 55296 bytes
#define HW_SMEM (2 * HW_STB)         // 110592 bytes

template<int EPI>
__global__ __launch_bounds__(256, 1) void hgemm_w(
    const __half* __restrict__ A, const __half* __restrict__ Bt,
    const float* __restrict__ bias, __half* __restrict__ C, int N, int K)
{
  extern __shared__ __half smh[];
  int tid = threadIdx.x, lane = tid & 31, warp = tid >> 5;
  int bx = blockIdx.x, by = blockIdx.y;
  int wm = (warp >> 2) * 64, wn = (warp & 3) * 64;
  int gid = lane >> 2, tig = lane & 3;

  int ld_r = tid >> 3;                 // 0..31
  int ld_k = (tid & 7) * 8;            // 0..56
  const __half* Ag = A + (size_t)(by * 128 + ld_r) * K + ld_k;
  const __half* Bg = Bt + (size_t)(bx * 256 + ld_r) * K + ld_k;

  uint32_t smb = s2u(smh);
  uint32_t asd = smb + (ld_r * 72 + ld_k) * 2;
  uint32_t bsd = smb + (HW_AF + ld_r * 72 + ld_k) * 2;

  uint32_t a_lm[4], b_lm[4];
  #pragma unroll
  for (int mi = 0; mi < 4; mi++)
    a_lm[mi] = smb + (((wm + mi * 16 + (lane & 15)) * 72) + ((lane >> 4) * 8)) * 2;
  #pragma unroll
  for (int tp = 0; tp < 4; tp++)
    b_lm[tp] = smb + (HW_AF
             + (wn + 16 * tp + ((lane & 16) ? 8 : 0) + (lane & 7)) * 72
             + ((lane & 8) ? 8 : 0)) * 2;

  float c[4][8][4];
  #pragma unroll
  for (int mi = 0; mi < 4; mi++)
    #pragma unroll
    for (int ni = 0; ni < 8; ni++)
      #pragma unroll
      for (int q = 0; q < 4; q++) c[mi][ni][q] = 0.f;

  int nk = K >> 6;
  auto issue = [&](int kb, int st){
    uint32_t off = st ? HW_STB : 0u;
    const __half* ag = Ag + (size_t)kb * 64;
    const __half* bg = Bg + (size_t)kb * 64;
    #pragma unroll
    for (int i = 0; i < 4; i++)
      cpa16(asd + off + i * 32 * 72 * 2, ag + (size_t)(32 * i) * K);
    #pragma unroll
    for (int i = 0; i < 8; i++)
      cpa16(bsd + off + i * 32 * 72 * 2, bg + (size_t)(32 * i) * K);
    cp_commit();
  };
  issue(0, 0);

  for (int kb = 0; kb < nk; kb++){
    int st = kb & 1;
    cp_wait0();
    __syncthreads();
    if (kb + 1 < nk) issue(kb + 1, st ^ 1);
    uint32_t soff = st ? HW_STB : 0u;
    #pragma unroll
    for (int ks = 0; ks < 4; ks++){
      uint32_t koff = soff + ks * 32;
      uint32_t a[4][4], b[8][2];
      #pragma unroll
      for (int mi = 0; mi < 4; mi++)
        ldmx4(a[mi], a_lm[mi] + koff);
      #pragma unroll
      for (int tp = 0; tp < 4; tp++){
        uint32_t r[4];
        ldmx4(r, b_lm[tp] + koff);
        b[2*tp][0] = r[0]; b[2*tp][1] = r[1];
        b[2*tp+1][0] = r[2]; b[2*tp+1][1] = r[3];
      }
      #pragma unroll
      for (int mi = 0; mi < 4; mi++)
        #pragma unroll
        for (int t = 0; t < 8; t++)
          mma16(c[mi][t], a[mi], b[t]);
    }
    __syncthreads();
  }

  #pragma unroll
  for (int ni = 0; ni < 8; ni++){
    int col = bx * 256 + wn + ni * 8 + 2 * tig;
    float bb0 = bias[col], bb1 = bias[col + 1];
    #pragma unroll
    for (int mi = 0; mi < 4; mi++){
      int row0 = by * 128 + wm + mi * 16 + gid;
      float v00 = c[mi][ni][0] + bb0, v01 = c[mi][ni][1] + bb1;
      float v10 = c[mi][ni][2] + bb0, v11 = c[mi][ni][3] + bb1;
      if (EPI == 1){
        v00 = gelu_exact(v00); v01 = gelu_exact(v01);
        v10 = gelu_exact(v10); v11 = gelu_exact(v11);
      }
      *(__half2*)&C[(size_t)row0 * N + col]       = __floats2half2_rn(v00, v01);
      *(__half2*)&C[(size_t)(row0 + 8) * N + col] = __floats2half2_rn(v10, v11);
    }
  }
}

// ---------------------------------------------------------------------------
// fp16 GEMM narrow: tile 128x128, BK=64, 2-stage dynamic smem, occ2, ldmatrix.
// bias + residual -> fp32.
// ---------------------------------------------------------------------------
#define HN_AF   (128 * 72)
#define HN_STF  (2 * HN_AF)          // A + B per stage = 18432 halves
#define HN_STB  (HN_STF * 2)         // 36864 bytes
#define HN_SMEM (2 * HN_STB)         // 73728 bytes

__global__ __launch_bounds__(256, 2) void hgemm_n(
    const __half* __restrict__ A, const __half* __restrict__ Bt,
    const float* __restrict__ bias, const float* __restrict__ res,
    float* __restrict__ C, int N, int K)
{
  extern __shared__ __half smh[];
  int tid = threadIdx.x, lane = tid & 31, warp = tid >> 5;
  int bx = blockIdx.x, by = blockIdx.y;
  int wm = (warp >> 2) * 64, wn = (warp & 3) * 32;
  int gid = lane >> 2, tig = lane & 3;

  int ld_r = tid >> 3;
  int ld_k = (tid & 7) * 8;
  const __half* Ag = A + (size_t)(by * 128 + ld_r) * K + ld_k;
  const __half* Bg = Bt + (size_t)(bx * 128 + ld_r) * K + ld_k;

  uint32_t smb = s2u(smh);
  uint32_t asd = smb + (ld_r * 72 + ld_k) * 2;
  uint32_t bsd = smb + (HN_AF + ld_r * 72 + ld_k) * 2;

  uint32_t a_lm[4], b_lm[2];
  #pragma unroll
  for (int mi = 0; mi < 4; mi++)
    a_lm[mi] = smb + (((wm + mi * 16 + (lane & 15)) * 72) + ((lane >> 4) * 8)) * 2;
  #pragma unroll
  for (int tp = 0; tp < 2; tp++)
    b_lm[tp] = smb + (HN_AF
             + (wn + 16 * tp + ((lane & 16) ? 8 : 0) + (lane & 7)) * 72
             + ((lane & 8) ? 8 : 0)) * 2;

  float c[4][4][4];
  #pragma unroll
  for (int mi = 0; mi < 4; mi++)
    #pragma unroll
    for (int ni = 0; ni < 4; ni++)
      #pragma unroll
      for (int q = 0; q < 4; q++) c[mi][ni][q] = 0.f;

  int nk = K >> 6;
  auto issue = [&](int kb, int st){
    uint32_t off = st ? HN_STB : 0u;
    const __half* ag = Ag + (size_t)kb * 64;
    const __half* bg = Bg + (size_t)kb * 64;
    #pragma unroll
    for (int i = 0; i < 4; i++){
      cpa16(asd + off + i * 32 * 72 * 2, ag + (size_t)(32 * i) * K);
      cpa16(bsd + off + i * 32 * 72 * 2, bg + (size_t)(32 * i) * K);
    }
    cp_commit();
  };
  issue(0, 0);

  for (int kb = 0; kb < nk; kb++){
    int st = kb & 1;
    cp_wait0();
    __syncthreads();
    if (kb + 1 < nk) issue(kb + 1, st ^ 1);
    uint32_t soff = st ? HN_STB : 0u;
    #pragma unroll
    for (int ks = 0; ks < 4; ks++){
      uint32_t koff = soff + ks * 32;
      uint32_t a[4][4], b[4][2];
      #pragma unroll
      for (int mi = 0; mi < 4; mi++)
        ldmx4(a[mi], a_lm[mi] + koff);
      #pragma unroll
      for (int tp = 0; tp < 2; tp++){
        uint32_t r[4];
        ldmx4(r, b_lm[tp] + koff);
        b[2*tp][0] = r[0]; b[2*tp][1] = r[1];
        b[2*tp+1][0] = r[2]; b[2*tp+1][1] = r[3];
      }
      #pragma unroll
      for (int mi = 0; mi < 4; mi++)
        #pragma unroll
        for (int t = 0; t < 4; t++)
          mma16(c[mi][t], a[mi], b[t]);
    }
    __syncthreads();
  }

  #pragma unroll
  for (int ni = 0; ni < 4; ni++){
    int col = bx * 128 + wn + ni * 8 + 2 * tig;
    float bb0 = bias[col], bb1 = bias[col + 1];
    #pragma unroll
    for (int mi = 0; mi < 4; mi++){
      int row0 = by * 128 + wm + mi * 16 + gid;
      float2 r0 = *(const float2*)&res[(size_t)row0 * N + col];
      float2 r1 = *(const float2*)&res[(size_t)(row0 + 8) * N + col];
      float2 v0 = make_float2(c[mi][ni][0] + bb0 + r0.x, c[mi][ni][1] + bb1 + r0.y);
      float2 v1 = make_float2(c[mi][ni][2] + bb0 + r1.x, c[mi][ni][3] + bb1 + r1.y);
      *(float2*)&C[(size_t)row0 * N + col]       = v0;
      *(float2*)&C[(size_t)(row0 + 8) * N + col] = v1;
    }
  }
}

// ---------------------------------------------------------------------------
// fp16 mma flash attention (unchanged from R10; K-tile 128).
// ---------------------------------------------------------------------------
#define AT_TF   (128 * 136)
#define AT_STF  (2 * AT_TF)
#define AT_SMEM (2 * AT_STF * 2)

__global__ __launch_bounds__(256, 1) void attn_h(
    const __half* __restrict__ qkv, __half* __restrict__ av)
{
  extern __shared__ __half smh[];
  uint32_t sbase = s2u(smh);

  int qt = blockIdx.x, bh = blockIdx.y;
  int b = bh >> 4, h = bh & 15;
  int q0 = qt * 128;
  int tid = threadIdx.x, warp = tid >> 5, lane = tid & 31;
  int gid = lane >> 2, tig = lane & 3;
  int wq = warp * 16;
  const float scl = 0.08838834764831845f;

  const __half* base = qkv + (size_t)(b * SEQ) * (3 * DMODEL) + h * 128;

  int r0 = q0 + wq + gid;
  const __half* Qp0 = base + (size_t)r0 * (3 * DMODEL);
  const __half* Qp1 = Qp0 + (size_t)8 * (3 * DMODEL);
  uint32_t qa[8][4];
  #pragma unroll
  for (int j = 0; j < 8; j++){
    qa[j][0] = *(const uint32_t*)(Qp0 + 16 * j + 2 * tig);
    qa[j][1] = *(const uint32_t*)(Qp1 + 16 * j + 2 * tig);
    qa[j][2] = *(const uint32_t*)(Qp0 + 16 * j + 2 * tig + 8);
    qa[j][3] = *(const uint32_t*)(Qp1 + 16 * j + 2 * tig + 8);
  }

  float O[16][4];
  #pragma unroll
  for (int u = 0; u < 16; u++)
    #pragma unroll
    for (int q = 0; q < 4; q++) O[u][q] = 0.f;
  float m0 = -1e30f, m1 = -1e30f, l0 = 0.f, l1 = 0.f;

  int ntiles = qt + 1;
  int pf_r = tid >> 4, pf_d = (tid & 15) * 8;

  auto prefetch = [&](int kt, int buf){
    uint32_t db = sbase + (uint32_t)buf * AT_STF * 2;
    const __half* kg = base + DMODEL + (size_t)(kt * 128 + pf_r) * (3 * DMODEL) + pf_d;
    #pragma unroll
    for (int it = 0; it < 8; it++){
      uint32_t dk = db + ((pf_r + it * 16) * 136 + pf_d) * 2;
      const __half* src = kg + (size_t)(it * 16) * (3 * DMODEL);
      cpa16(dk, src);
      cpa16(dk + AT_TF * 2, src + DMODEL);
    }
    cp_commit();
  };
  prefetch(0, 0);

  for (int kt = 0; kt < ntiles; kt++){
    int buf = kt & 1;
    if (kt + 1 < ntiles){ prefetch(kt + 1, buf ^ 1); cp_wait1(); }
    else cp_wait0();
    __syncthreads();

    int k0 = kt * 128;
    {
      const __half* Ks = smh + buf * AT_STF;

      float s[16][4];
      #pragma unroll
      for (int t = 0; t < 16; t++)
        #pragma unroll
        for (int q = 0; q < 4; q++) s[t][q] = 0.f;
      #pragma unroll
      for (int j = 0; j < 8; j++){
        #pragma unroll
        for (int t = 0; t < 16; t++){
          const __half* bb = Ks + (8 * t + gid) * 136 + 16 * j;
          uint32_t bf[2];
          bf[0] = *(const uint32_t*)(bb + 2 * tig);
          bf[1] = *(const uint32_t*)(bb + 2 * tig + 8);
          mma16(s[t], qa[j], bf);
        }
      }

      bool dg = (kt == qt);
      float mx0 = -1e30f, mx1 = -1e30f;
      #pragma unroll
      for (int t = 0; t < 16; t++){
        float c0 = s[t][0] * scl, c1 = s[t][1] * scl;
        float c2 = s[t][2] * scl, c3 = s[t][3] * scl;
        if (dg){
          int g0 = k0 + 8 * t + 2 * tig;
          if (g0     > r0)     c0 = -1e30f;
          if (g0 + 1 > r0)     c1 = -1e30f;
          if (g0     > r0 + 8) c2 = -1e30f;
          if (g0 + 1 > r0 + 8) c3 = -1e30f;
        }
        s[t][0] = c0; s[t][1] = c1; s[t][2] = c2; s[t][3] = c3;
        mx0 = fmaxf(mx0, fmaxf(c0, c1));
        mx1 = fmaxf(mx1, fmaxf(c2, c3));
      }
      #pragma unroll
      for (int m = 1; m < 4; m <<= 1){
        mx0 = fmaxf(mx0, __shfl_xor_sync(0xffffffffu, mx0, m));
        mx1 = fmaxf(mx1, __shfl_xor_sync(0xffffffffu, mx1, m));
      }
      float mn0 = fmaxf(m0, mx0), mn1 = fmaxf(m1, mx1);
      float cr0 = __expf(m0 - mn0), cr1 = __expf(m1 - mn1);
      m0 = mn0; m1 = mn1;
      float ls0 = 0.f, ls1 = 0.f;
      #pragma unroll
      for (int t = 0; t < 16; t++){
        s[t][0] = __expf(s[t][0] - mn0);
        s[t][1] = __expf(s[t][1] - mn0);
        s[t][2] = __expf(s[t][2] - mn1);
        s[t][3] = __expf(s[t][3] - mn1);
        ls0 += s[t][0] + s[t][1];
        ls1 += s[t][2] + s[t][3];
      }
      #pragma unroll
      for (int m = 1; m < 4; m <<= 1){
        ls0 += __shfl_xor_sync(0xffffffffu, ls0, m);
        ls1 += __shfl_xor_sync(0xffffffffu, ls1, m);
      }
      l0 = l0 * cr0 + ls0;
      l1 = l1 * cr1 + ls1;
      #pragma unroll
      for (int u = 0; u < 16; u++){
        O[u][0] *= cr0; O[u][1] *= cr0;
        O[u][2] *= cr1; O[u][3] *= cr1;
      }

      #pragma unroll
      for (int j2 = 0; j2 < 8; j2++){
        uint32_t pa[4];
        pa[0] = packh2(s[2*j2][0],   s[2*j2][1]);
        pa[1] = packh2(s[2*j2][2],   s[2*j2][3]);
        pa[2] = packh2(s[2*j2+1][0], s[2*j2+1][1]);
        pa[3] = packh2(s[2*j2+1][2], s[2*j2+1][3]);
        uint32_t vrow = sbase + (uint32_t)buf * AT_STF * 2 + AT_TF * 2
                      + ((16 * j2 + (lane & 15)) * 136) * 2;
        #pragma unroll
        for (int u = 0; u < 16; u++){
          uint32_t b0, b1;
          ldmx2t(b0, b1, vrow + 16 * u);
          uint32_t bf[2] = {b0, b1};
          mma16(O[u], pa, bf);
        }
      }
    }
    __syncthreads();
  }

  float i0 = 1.0f / l0, i1 = 1.0f / l1;
  __half* o0 = av + ((size_t)(b * SEQ) + r0) * DMODEL + h * 128;
  __half* o1 = o0 + (size_t)8 * DMODEL;
  #pragma unroll
  for (int u = 0; u < 16; u++){
    *(__half2*)&o0[8 * u + 2 * tig] = __floats2half2_rn(O[u][0] * i0, O[u][1] * i0);
    *(__half2*)&o1[8 * u + 2 * tig] = __floats2half2_rn(O[u][2] * i1, O[u][3] * i1);
  }
}

// ---------------- launch ----------------
extern "C" void kernel_launch(void* const* d_in, const int* in_sizes, int n_in,
                              void* d_out, int out_size)
{
  const float* x     = (const float*)d_in[0];
  const float* ln1_g = (const float*)d_in[1];
  const float* ln1_b = (const float*)d_in[2];
  const float* qkv_w = (const float*)d_in[3];
  const float* qkv_b = (const float*)d_in[4];
  const float* out_w = (const float*)d_in[5];
  const float* out_b = (const float*)d_in[6];
  const float* ln2_g = (const float*)d_in[7];
  const float* ln2_b = (const float*)d_in[8];
  const float* w1    = (const float*)d_in[9];
  const float* b1    = (const float*)d_in[10];
  const float* w2    = (const float*)d_in[11];
  const float* b2    = (const float*)d_in[12];
  float* out = (float*)d_out;

  __half *h_p, *qkv_p, *av_p, *ffn_p, *wqkv_p, *wout_p, *w1_p, *w2_p;
  float *x1_p;
  cudaGetSymbolAddress((void**)&h_p,    g_h);
  cudaGetSymbolAddress((void**)&qkv_p,  g_qkv);
  cudaGetSymbolAddress((void**)&av_p,   g_av);
  cudaGetSymbolAddress((void**)&x1_p,   g_x1);
  cudaGetSymbolAddress((void**)&ffn_p,  g_ffn);
  cudaGetSymbolAddress((void**)&wqkv_p, g_wqkv);
  cudaGetSymbolAddress((void**)&wout_p, g_wout);
  cudaGetSymbolAddress((void**)&w1_p,   g_w1);
  cudaGetSymbolAddress((void**)&w2_p,   g_w2);

  cudaFuncSetAttribute(attn_h, cudaFuncAttributeMaxDynamicSharedMemorySize, AT_SMEM);
  cudaFuncSetAttribute(hgemm_w<0>, cudaFuncAttributeMaxDynamicSharedMemorySize, HW_SMEM);
  cudaFuncSetAttribute(hgemm_w<1>, cudaFuncAttributeMaxDynamicSharedMemorySize, HW_SMEM);
  cudaFuncSetAttribute(hgemm_n, cudaFuncAttributeMaxDynamicSharedMemorySize, HN_SMEM);

  wtrans_all<<<WT_TILES, 256>>>(qkv_w, wqkv_p, out_w, wout_p, w1, w1_p, w2, w2_p);

  ln_kernel<<<NTOK, 256>>>(x, ln1_g, ln1_b, h_p);

  hgemm_w<0><<<dim3(24, 32), 256, HW_SMEM>>>(h_p, wqkv_p, qkv_b, qkv_p,
                                             3 * DMODEL, DMODEL);

  attn_h<<<dim3(SEQ / 128, 2 * NHEAD), 256, AT_SMEM>>>(qkv_p, av_p);

  hgemm_n<<<dim3(16, 32), 256, HN_SMEM>>>(av_p, wout_p, out_b, x, x1_p,
                                          DMODEL, DMODEL);

  ln_kernel<<<NTOK, 256>>>(x1_p, ln2_g, ln2_b, h_p);

  hgemm_w<1><<<dim3(32, 32), 256, HW_SMEM>>>(h_p, w1_p, b1, ffn_p, FFDIM, DMODEL);

  hgemm_n<<<dim3(16, 32), 256, HN_SMEM>>>(ffn_p, w2_p, b2, x1_p, out,
                                          DMODEL, FFDIM);
}